// round 1
// baseline (speedup 1.0000x reference)
#include <cuda_runtime.h>

#define Hdim 128
#define HALF 64
#define NMAX 200000
#define EMAX 400000
#define T 256
#define RTILE 64
#define RP 68            // padded row stride for transposed smem input
#define WC 64            // weight K-chunk staged in smem

typedef unsigned long long ull;

// ---- scratch (static __device__; no allocations allowed) ----
__device__ float g_agg[(size_t)NMAX * HALF];
__device__ float g_xc1[(size_t)NMAX * Hdim];
__device__ float g_xc2[(size_t)NMAX * Hdim];

// ---- packed fp32x2 helpers (sm_100+) ----
__device__ __forceinline__ ull dup2(float x) {
    ull r; asm("mov.b64 %0, {%1, %1};" : "=l"(r) : "f"(x)); return r;
}
__device__ __forceinline__ ull fma2(ull a, ull b, ull c) {
    ull d; asm("fma.rn.f32x2 %0, %1, %2, %3;" : "=l"(d) : "l"(a), "l"(b), "l"(c)); return d;
}
__device__ __forceinline__ float2 unpk(ull v) {
    float lo, hi; asm("mov.b64 {%0, %1}, %2;" : "=f"(lo), "=f"(hi) : "l"(v));
    return make_float2(lo, hi);
}
__device__ __forceinline__ float silu_f(float v) {
    return v * (1.0f / (1.0f + __expf(-v)));
}

// ---- zero the aggregation buffer ----
__global__ void k_zero(int n) {
    int i = blockIdx.x * blockDim.x + threadIdx.x;
    if (i < n) g_agg[i] = 0.0f;
}

// ---- scatter: agg[recv][0:64] += ea[e][0:64]; agg[send][0:64] += ea[e][64:128] ----
__global__ void k_scatter(const float* __restrict__ ea, const int* __restrict__ ei, int E) {
    int gid = blockIdx.x * blockDim.x + threadIdx.x;
    int e = gid >> 5;
    if (e >= E) return;
    int c4 = (gid & 31) << 2;
    float4 v = *(const float4*)(ea + (size_t)e * Hdim + c4);
    int base;
    if (c4 < HALF) {
        int r = ei[E + e];           // receivers = edge_index[1]
        base = r * HALF + c4;
    } else {
        int s = ei[e];               // senders = edge_index[0]
        base = s * HALF + (c4 - HALF);
    }
    atomicAdd(&g_agg[base + 0], v.x);
    atomicAdd(&g_agg[base + 1], v.y);
    atomicAdd(&g_agg[base + 2], v.z);
    atomicAdd(&g_agg[base + 3], v.w);
}

// ---- GEMM tile: acc[r][p] (f32x2 over a col-pair) += in[k][rows] * W[k][cols] ----
// s_in layout: transposed [k][row] with stride RP. W: row-major [K][128] in gmem.
__device__ __forceinline__ void gemm_tile(const float* __restrict__ W, int K,
                                          const float* s_in, float* s_w,
                                          ull acc[4][4], int tid, int ci, int r0)
{
#pragma unroll
    for (int r = 0; r < 4; r++)
#pragma unroll
        for (int p = 0; p < 4; p++) acc[r][p] = 0ull;

    for (int kb = 0; kb < K; kb += WC) {
        __syncthreads();   // protect s_w reuse (and first time: staging of s_in)
        {
            const float4* wg = (const float4*)(W + (size_t)kb * Hdim);
            float4* sw4 = (float4*)s_w;
#pragma unroll
            for (int i = 0; i < (WC * Hdim / 4) / T; i++)
                sw4[tid + i * T] = wg[tid + i * T];
        }
        __syncthreads();
#pragma unroll 4
        for (int k = 0; k < WC; k++) {
            float4 a = *(const float4*)(s_in + (kb + k) * RP + r0);
            ull a0 = dup2(a.x), a1 = dup2(a.y), a2 = dup2(a.z), a3 = dup2(a.w);
            ulonglong2 wa = *(const ulonglong2*)(s_w + k * Hdim + ci);
            ulonglong2 wb = *(const ulonglong2*)(s_w + k * Hdim + ci + 4);
            acc[0][0] = fma2(a0, wa.x, acc[0][0]);
            acc[0][1] = fma2(a0, wa.y, acc[0][1]);
            acc[0][2] = fma2(a0, wb.x, acc[0][2]);
            acc[0][3] = fma2(a0, wb.y, acc[0][3]);
            acc[1][0] = fma2(a1, wa.x, acc[1][0]);
            acc[1][1] = fma2(a1, wa.y, acc[1][1]);
            acc[1][2] = fma2(a1, wb.x, acc[1][2]);
            acc[1][3] = fma2(a1, wb.y, acc[1][3]);
            acc[2][0] = fma2(a2, wa.x, acc[2][0]);
            acc[2][1] = fma2(a2, wa.y, acc[2][1]);
            acc[2][2] = fma2(a2, wb.x, acc[2][2]);
            acc[2][3] = fma2(a2, wb.y, acc[2][3]);
            acc[3][0] = fma2(a3, wa.x, acc[3][0]);
            acc[3][1] = fma2(a3, wa.y, acc[3][1]);
            acc[3][2] = fma2(a3, wb.x, acc[3][2]);
            acc[3][3] = fma2(a3, wb.y, acc[3][3]);
        }
    }
    __syncthreads();   // all s_in reads done before caller overwrites it
}

// ---- bias + SiLU, write activations back (transposed) into s_in ----
__device__ __forceinline__ void act_store(const float* __restrict__ bias,
                                          float* s_in, ull acc[4][4], int ci, int r0)
{
    float2 bv[4];
#pragma unroll
    for (int p = 0; p < 4; p++) bv[p] = ((const float2*)bias)[(ci >> 1) + p];
    float vals[4][8];
#pragma unroll
    for (int r = 0; r < 4; r++)
#pragma unroll
        for (int p = 0; p < 4; p++) {
            float2 v = unpk(acc[r][p]);
            vals[r][2 * p]     = silu_f(v.x + bv[p].x);
            vals[r][2 * p + 1] = silu_f(v.y + bv[p].y);
        }
#pragma unroll
    for (int c = 0; c < 8; c++) {
        float4 col = make_float4(vals[0][c], vals[1][c], vals[2][c], vals[3][c]);
        *(float4*)(s_in + (ci + c) * RP + r0) = col;
    }
}

// ---- bias + layernorm + (optional residual) output ----
__device__ __forceinline__ void ln_out(const float* __restrict__ bias,
                                       const float* __restrict__ gamma,
                                       const float* __restrict__ beta,
                                       ull acc[4][4], int ci, int r0,
                                       int rowbase, int nrows,
                                       float* out1, const float* resid, float* out2)
{
    float2 bv[4];
#pragma unroll
    for (int p = 0; p < 4; p++) bv[p] = ((const float2*)bias)[(ci >> 1) + p];
    float vals[4][8];
#pragma unroll
    for (int r = 0; r < 4; r++)
#pragma unroll
        for (int p = 0; p < 4; p++) {
            float2 v = unpk(acc[r][p]);
            vals[r][2 * p]     = v.x + bv[p].x;
            vals[r][2 * p + 1] = v.y + bv[p].y;
        }
    float4 g0 = *(const float4*)(gamma + ci);
    float4 g1 = *(const float4*)(gamma + ci + 4);
    float4 t0 = *(const float4*)(beta + ci);
    float4 t1 = *(const float4*)(beta + ci + 4);
    float gv[8] = {g0.x, g0.y, g0.z, g0.w, g1.x, g1.y, g1.z, g1.w};
    float bt[8] = {t0.x, t0.y, t0.z, t0.w, t1.x, t1.y, t1.z, t1.w};

#pragma unroll
    for (int r = 0; r < 4; r++) {
        float s = 0.0f, q = 0.0f;
#pragma unroll
        for (int c = 0; c < 8; c++) { s += vals[r][c]; q += vals[r][c] * vals[r][c]; }
        // reduce across the 16 threads (lanes differing in tid&15) sharing this row group
#pragma unroll
        for (int off = 8; off; off >>= 1) {
            s += __shfl_xor_sync(0xffffffffu, s, off);
            q += __shfl_xor_sync(0xffffffffu, q, off);
        }
        float mu = s * (1.0f / Hdim);
        float inv = rsqrtf(q * (1.0f / Hdim) - mu * mu + 1e-5f);
        int row = rowbase + r0 + r;
        if (row < nrows) {
            float o[8];
#pragma unroll
            for (int c = 0; c < 8; c++)
                o[c] = (vals[r][c] - mu) * inv * gv[c] + bt[c];
            size_t base = (size_t)row * Hdim + ci;
            if (out1) {
                *(float4*)(out1 + base)     = make_float4(o[0], o[1], o[2], o[3]);
                *(float4*)(out1 + base + 4) = make_float4(o[4], o[5], o[6], o[7]);
            }
            if (out2) {
                float4 r0v = *(const float4*)(resid + base);
                float4 r1v = *(const float4*)(resid + base + 4);
                *(float4*)(out2 + base)     = make_float4(o[0] + r0v.x, o[1] + r0v.y, o[2] + r0v.z, o[3] + r0v.w);
                *(float4*)(out2 + base + 4) = make_float4(o[4] + r1v.x, o[5] + r1v.y, o[6] + r1v.z, o[7] + r1v.w);
            }
        }
    }
}

// ---- CellBlock MLP: in = [xin | agg] (192) -> 128 -> 128 -> LN ----
__global__ void __launch_bounds__(T) k_cell(const float* __restrict__ xin,
    const float* __restrict__ w1, const float* __restrict__ b1,
    const float* __restrict__ w2, const float* __restrict__ b2,
    const float* __restrict__ w3, const float* __restrict__ b3,
    const float* __restrict__ gam, const float* __restrict__ bet,
    float* out1, const float* resid, float* out2, int nrows)
{
    extern __shared__ float smem[];
    float* s_in = smem;
    float* s_w = smem + 192 * RP;
    int tid = threadIdx.x;
    int rowbase = blockIdx.x * RTILE;

    for (int idx = tid; idx < RTILE * 192; idx += T) {
        int r = idx / 192, k = idx - r * 192;
        int row = rowbase + r; if (row >= nrows) row = nrows - 1;
        float v = (k < Hdim) ? xin[(size_t)row * Hdim + k]
                             : g_agg[(size_t)row * HALF + (k - Hdim)];
        s_in[k * RP + r] = v;
    }

    int ci = (tid & 15) * 8;
    int r0 = (tid >> 4) * 4;
    ull acc[4][4];
    gemm_tile(w1, 192, s_in, s_w, acc, tid, ci, r0);
    act_store(b1, s_in, acc, ci, r0);
    gemm_tile(w2, 128, s_in, s_w, acc, tid, ci, r0);
    act_store(b2, s_in, acc, ci, r0);
    gemm_tile(w3, 128, s_in, s_w, acc, tid, ci, r0);
    ln_out(b3, gam, bet, acc, ci, r0, rowbase, nrows, out1, resid, out2);
}

// ---- EdgeBlock MLP: in = [ea | xc[send] | xc[recv]] (384) -> 128 -> 128 -> LN ----
__global__ void __launch_bounds__(T) k_edge(const float* __restrict__ ea,
    const float* __restrict__ xc, const int* __restrict__ ei,
    const float* __restrict__ w1, const float* __restrict__ b1,
    const float* __restrict__ w2, const float* __restrict__ b2,
    const float* __restrict__ w3, const float* __restrict__ b3,
    const float* __restrict__ gam, const float* __restrict__ bet,
    float* out2, int E, int N)
{
    extern __shared__ float smem[];
    float* s_in = smem;
    float* s_w = smem + 384 * RP;
    int tid = threadIdx.x;
    int rowbase = blockIdx.x * RTILE;

    for (int idx = tid; idx < RTILE * 384; idx += T) {
        int r = idx / 384, k = idx - r * 384;
        int row = rowbase + r; if (row >= E) row = E - 1;
        float v;
        if (k < Hdim) {
            v = ea[(size_t)row * Hdim + k];
        } else if (k < 2 * Hdim) {
            int sidx = ei[row];
            v = xc[(size_t)sidx * Hdim + (k - Hdim)];
        } else {
            int ridx = ei[E + row];
            v = xc[(size_t)ridx * Hdim + (k - 2 * Hdim)];
        }
        s_in[k * RP + r] = v;
    }

    int ci = (tid & 15) * 8;
    int r0 = (tid >> 4) * 4;
    ull acc[4][4];
    gemm_tile(w1, 384, s_in, s_w, acc, tid, ci, r0);
    act_store(b1, s_in, acc, ci, r0);
    gemm_tile(w2, 128, s_in, s_w, acc, tid, ci, r0);
    act_store(b2, s_in, acc, ci, r0);
    gemm_tile(w3, 128, s_in, s_w, acc, tid, ci, r0);
    ln_out(b3, gam, bet, acc, ci, r0, rowbase, E, nullptr, ea, out2);
}

static const int SMEM_CELL = (192 * RP + WC * Hdim) * 4;   // 84992 B
static const int SMEM_EDGE = (384 * RP + WC * Hdim) * 4;   // 137216 B

extern "C" void kernel_launch(void* const* d_in, const int* in_sizes, int n_in,
                              void* d_out, int out_size)
{
    const float* x     = (const float*)d_in[0];
    const float* ea    = (const float*)d_in[1];
    const float* cb_w1 = (const float*)d_in[2];
    const float* cb_b1 = (const float*)d_in[3];
    const float* cb_w2 = (const float*)d_in[4];
    const float* cb_b2 = (const float*)d_in[5];
    const float* cb_w3 = (const float*)d_in[6];
    const float* cb_b3 = (const float*)d_in[7];
    const float* cb_g  = (const float*)d_in[8];
    const float* cb_be = (const float*)d_in[9];
    const float* eb_w1 = (const float*)d_in[10];
    const float* eb_b1 = (const float*)d_in[11];
    const float* eb_w2 = (const float*)d_in[12];
    const float* eb_b2 = (const float*)d_in[13];
    const float* eb_w3 = (const float*)d_in[14];
    const float* eb_b3 = (const float*)d_in[15];
    const float* eb_g  = (const float*)d_in[16];
    const float* eb_be = (const float*)d_in[17];
    const int*   ei    = (const int*)d_in[18];

    int N = in_sizes[0] / Hdim;
    int E = in_sizes[1] / Hdim;
    float* out_x = (float*)d_out;
    float* out_e = out_x + (size_t)N * Hdim;

    float *xc1, *xc2;
    cudaGetSymbolAddress((void**)&xc1, g_xc1);
    cudaGetSymbolAddress((void**)&xc2, g_xc2);

    cudaFuncSetAttribute(k_cell, cudaFuncAttributeMaxDynamicSharedMemorySize, SMEM_CELL);
    cudaFuncSetAttribute(k_edge, cudaFuncAttributeMaxDynamicSharedMemorySize, SMEM_EDGE);

    // 1) agg = scatter of original edge_attr (loop-invariant -> computed once)
    k_zero<<<(N * HALF + 255) / 256, 256>>>(N * HALF);
    k_scatter<<<(E * 32 + 255) / 256, 256>>>(ea, ei, E);

    int cgrid = (N + RTILE - 1) / RTILE;
    int egrid = (E + RTILE - 1) / RTILE;

    // 2) two CellBlock rounds (shared weights, same agg)
    k_cell<<<cgrid, T, SMEM_CELL>>>(x,   cb_w1, cb_b1, cb_w2, cb_b2, cb_w3, cb_b3,
                                    cb_g, cb_be, xc1, nullptr, nullptr, N);
    k_cell<<<cgrid, T, SMEM_CELL>>>(xc1, cb_w1, cb_b1, cb_w2, cb_b2, cb_w3, cb_b3,
                                    cb_g, cb_be, xc2, x, out_x, N);

    // 3) EdgeBlock + residual
    k_edge<<<egrid, T, SMEM_EDGE>>>(ea, xc2, ei,
                                    eb_w1, eb_b1, eb_w2, eb_b2, eb_w3, eb_b3,
                                    eb_g, eb_be, out_e, E, N);
}

// round 3
// speedup vs baseline: 2.1481x; 2.1481x over previous
#include <cuda_runtime.h>
#include <cuda_bf16.h>
#include <cstdint>

#define Hdim 128
#define HALF 64
#define NMAX 200000
#define T 256
#define SA 136   // smem row stride in bf16 elements (stride*2 ≡ 16 mod 128 → ldmatrix conflict-free)

// ---------------- static device scratch ----------------
__device__ float g_agg[(size_t)NMAX * HALF];
__device__ float g_xc1[(size_t)NMAX * Hdim];
__device__ float g_xc2[(size_t)NMAX * Hdim];
// transposed bf16 weights [n=128][K], hi + lo split
// offsets: cb1(K=192):0  cb2(128):24576  cb3(128):40960  eb1(384):57344  eb2(128):106496  eb3(128):122880
__device__ __nv_bfloat16 g_wth[139264];
__device__ __nv_bfloat16 g_wtl[139264];

// ---------------- helpers ----------------
__device__ __forceinline__ uint32_t smem_u32(const void* p) {
    uint32_t a;
    asm("{ .reg .u64 t; cvta.to.shared.u64 t, %1; cvt.u32.u64 %0, t; }" : "=r"(a) : "l"(p));
    return a;
}
__device__ __forceinline__ void ldsm4(uint32_t r[4], uint32_t a) {
    asm volatile("ldmatrix.sync.aligned.m8n8.x4.shared.b16 {%0,%1,%2,%3}, [%4];"
        : "=r"(r[0]), "=r"(r[1]), "=r"(r[2]), "=r"(r[3]) : "r"(a));
}
__device__ __forceinline__ void mma16816(float d[4], const uint32_t a[4], uint32_t b0, uint32_t b1) {
    asm volatile("mma.sync.aligned.m16n8k16.row.col.f32.bf16.bf16.f32 "
        "{%0,%1,%2,%3}, {%4,%5,%6,%7}, {%8,%9}, {%0,%1,%2,%3};"
        : "+f"(d[0]), "+f"(d[1]), "+f"(d[2]), "+f"(d[3])
        : "r"(a[0]), "r"(a[1]), "r"(a[2]), "r"(a[3]), "r"(b0), "r"(b1));
}
__device__ __forceinline__ void split2(float a, float b, uint32_t& hi, uint32_t& lo) {
    __nv_bfloat162 h = __floats2bfloat162_rn(a, b);
    float2 hf = __bfloat1622float2(h);
    __nv_bfloat162 l = __floats2bfloat162_rn(a - hf.x, b - hf.y);
    hi = *reinterpret_cast<uint32_t*>(&h);
    lo = *reinterpret_cast<uint32_t*>(&l);
}
__device__ __forceinline__ float silu_f(float v) {
    return v * (1.0f / (1.0f + __expf(-v)));
}

// ---------------- small kernels ----------------
__global__ void k_zero(int n) {
    int i = blockIdx.x * blockDim.x + threadIdx.x;
    if (i < n) g_agg[i] = 0.0f;
}
__global__ void k_scatter(const float* __restrict__ ea, const int* __restrict__ ei, int E) {
    int gid = blockIdx.x * blockDim.x + threadIdx.x;
    int e = gid >> 5;
    if (e >= E) return;
    int c4 = (gid & 31) << 2;
    float4 v = *(const float4*)(ea + (size_t)e * Hdim + c4);
    int base;
    if (c4 < HALF) { int r = ei[E + e]; base = r * HALF + c4; }
    else           { int s = ei[e];     base = s * HALF + (c4 - HALF); }
    atomicAdd(&g_agg[base + 0], v.x);
    atomicAdd(&g_agg[base + 1], v.y);
    atomicAdd(&g_agg[base + 2], v.z);
    atomicAdd(&g_agg[base + 3], v.w);
}
// transpose W[K,128] fp32 -> WT[128,K] bf16 hi/lo
__global__ void k_prep(const float* __restrict__ w, int K, int dstoff) {
    int idx = blockIdx.x * blockDim.x + threadIdx.x;
    if (idx >= K * Hdim) return;
    int k = idx >> 7, n = idx & 127;
    float v = w[idx];
    __nv_bfloat16 h = __float2bfloat16(v);
    __nv_bfloat16 l = __float2bfloat16(v - __bfloat162float(h));
    g_wth[dstoff + n * K + k] = h;
    g_wtl[dstoff + n * K + k] = l;
}

// ---------------- staging ----------------
__device__ __forceinline__ void stage_src(const float* __restrict__ src, int ld,
    int rowbase, int nrows, int ck, char* s_ah, char* s_al, int tid)
{
    int cw = ck >> 2;
    int tot = 128 * cw;
    for (int idx = tid; idx < tot; idx += T) {
        int r = idx / cw, c4 = (idx % cw) * 4;
        int grow = rowbase + r; if (grow >= nrows) grow = nrows - 1;
        float4 v = *(const float4*)(src + (size_t)grow * ld + c4);
        uint32_t h0, l0, h1, l1;
        split2(v.x, v.y, h0, l0);
        split2(v.z, v.w, h1, l1);
        size_t off = ((size_t)r * SA + c4) * 2;
        *(uint2*)(s_ah + off) = make_uint2(h0, h1);
        *(uint2*)(s_al + off) = make_uint2(l0, l1);
    }
}
__device__ __forceinline__ void stage_gather(const float* __restrict__ xc,
    const int* __restrict__ idxv, int rowbase, char* s_ah, char* s_al, int tid)
{
    for (int idx = tid; idx < 128 * 32; idx += T) {
        int r = idx >> 5, c4 = (idx & 31) * 4;
        int g = __ldg(idxv + rowbase + r);
        float4 v = *(const float4*)(xc + (size_t)g * Hdim + c4);
        uint32_t h0, l0, h1, l1;
        split2(v.x, v.y, h0, l0);
        split2(v.z, v.w, h1, l1);
        size_t off = ((size_t)r * SA + c4) * 2;
        *(uint2*)(s_ah + off) = make_uint2(h0, h1);
        *(uint2*)(s_al + off) = make_uint2(l0, l1);
    }
}
__device__ __forceinline__ void stage_b(const __nv_bfloat16* __restrict__ wh,
    const __nv_bfloat16* __restrict__ wl, int K, int kb, int ck,
    char* s_bh, char* s_bl, int tid)
{
    int cw = ck >> 2;
    int tot = 128 * cw;
    for (int idx = tid; idx < tot; idx += T) {
        int n = idx / cw, c4 = (idx % cw) * 4;
        size_t g = (size_t)n * K + kb + c4;
        uint2 h = *(const uint2*)(wh + g);
        uint2 l = *(const uint2*)(wl + g);
        size_t off = ((size_t)n * SA + c4) * 2;
        *(uint2*)(s_bh + off) = h;
        *(uint2*)(s_bl + off) = l;
    }
}

// ---------------- mma mainloop over one K-chunk ----------------
__device__ __forceinline__ void mma_chunk(uint32_t ah_base, uint32_t al_base,
    uint32_t bh_base, uint32_t bl_base, int nks, float acc[2][8][4], int w, int lane)
{
    int rg = w & 3, cg = w >> 2;
    int a_r = (lane & 7) + ((lane >> 3) & 1) * 8;
    int a_c = (lane >> 4) * 8;
    int b_r = (lane & 7) + (lane >> 4) * 8;
    int b_c = ((lane >> 3) & 1) * 8;
    uint32_t aoff0 = ((uint32_t)(rg * 32 + a_r) * SA + a_c) * 2;
    uint32_t aoff1 = ((uint32_t)(rg * 32 + 16 + a_r) * SA + a_c) * 2;
    uint32_t boff  = ((uint32_t)(cg * 64 + b_r) * SA + b_c) * 2;
    for (int ks = 0; ks < nks; ks++) {
        uint32_t kb2 = (uint32_t)ks * 32;
        uint32_t ah0[4], al0[4], ah1[4], al1[4];
        ldsm4(ah0, ah_base + aoff0 + kb2);
        ldsm4(al0, al_base + aoff0 + kb2);
        ldsm4(ah1, ah_base + aoff1 + kb2);
        ldsm4(al1, al_base + aoff1 + kb2);
#pragma unroll
        for (int p = 0; p < 4; p++) {
            uint32_t bh[4], bl[4];
            uint32_t bo = boff + kb2 + (uint32_t)p * (16 * SA * 2);
            ldsm4(bh, bh_base + bo);
            ldsm4(bl, bl_base + bo);
            mma16816(acc[0][2 * p],     ah0, bh[0], bh[1]);
            mma16816(acc[0][2 * p],     ah0, bl[0], bl[1]);
            mma16816(acc[0][2 * p],     al0, bh[0], bh[1]);
            mma16816(acc[0][2 * p + 1], ah0, bh[2], bh[3]);
            mma16816(acc[0][2 * p + 1], ah0, bl[2], bl[3]);
            mma16816(acc[0][2 * p + 1], al0, bh[2], bh[3]);
            mma16816(acc[1][2 * p],     ah1, bh[0], bh[1]);
            mma16816(acc[1][2 * p],     ah1, bl[0], bl[1]);
            mma16816(acc[1][2 * p],     al1, bh[0], bh[1]);
            mma16816(acc[1][2 * p + 1], ah1, bh[2], bh[3]);
            mma16816(acc[1][2 * p + 1], ah1, bl[2], bl[3]);
            mma16816(acc[1][2 * p + 1], al1, bh[2], bh[3]);
        }
    }
}
__device__ __forceinline__ void zero_acc(float acc[2][8][4]) {
#pragma unroll
    for (int m = 0; m < 2; m++)
#pragma unroll
        for (int t = 0; t < 8; t++)
#pragma unroll
            for (int i = 0; i < 4; i++) acc[m][t][i] = 0.0f;
}

// ---------------- epilogues ----------------
__device__ __forceinline__ void epi_act(float acc[2][8][4], const float* __restrict__ bias,
    char* s_ah, char* s_al, int w, int lane)
{
    int rg = w & 3, cg = w >> 2;
    int c2 = (lane & 3) * 2;
    int r0 = rg * 32 + (lane >> 2);
#pragma unroll
    for (int mt = 0; mt < 2; mt++)
#pragma unroll
        for (int nt = 0; nt < 8; nt++) {
            int col = cg * 64 + nt * 8 + c2;
            float2 b = __ldg((const float2*)(bias + col));
            float v0 = silu_f(acc[mt][nt][0] + b.x);
            float v1 = silu_f(acc[mt][nt][1] + b.y);
            float v2 = silu_f(acc[mt][nt][2] + b.x);
            float v3 = silu_f(acc[mt][nt][3] + b.y);
            uint32_t h, l;
            int row = r0 + mt * 16;
            split2(v0, v1, h, l);
            *(uint32_t*)(s_ah + ((size_t)row * SA + col) * 2) = h;
            *(uint32_t*)(s_al + ((size_t)row * SA + col) * 2) = l;
            split2(v2, v3, h, l);
            row += 8;
            *(uint32_t*)(s_ah + ((size_t)row * SA + col) * 2) = h;
            *(uint32_t*)(s_al + ((size_t)row * SA + col) * 2) = l;
        }
}
__device__ __forceinline__ void epi_ln(float acc[2][8][4],
    const float* __restrict__ bias, const float* __restrict__ gam, const float* __restrict__ bet,
    float* s_red, int rowbase, int nrows,
    float* out1, const float* __restrict__ resid, float* out2, int w, int lane)
{
    int rg = w & 3, cg = w >> 2;
    int c2 = (lane & 3) * 2;
    float vals[2][2][16];
#pragma unroll
    for (int mt = 0; mt < 2; mt++)
#pragma unroll
        for (int nt = 0; nt < 8; nt++) {
            int col = cg * 64 + nt * 8 + c2;
            float2 b = __ldg((const float2*)(bias + col));
            vals[mt][0][2 * nt]     = acc[mt][nt][0] + b.x;
            vals[mt][0][2 * nt + 1] = acc[mt][nt][1] + b.y;
            vals[mt][1][2 * nt]     = acc[mt][nt][2] + b.x;
            vals[mt][1][2 * nt + 1] = acc[mt][nt][3] + b.y;
        }
#pragma unroll
    for (int mt = 0; mt < 2; mt++)
#pragma unroll
        for (int h = 0; h < 2; h++) {
            float s = 0.0f, q = 0.0f;
#pragma unroll
            for (int j = 0; j < 16; j++) { float v = vals[mt][h][j]; s += v; q += v * v; }
            s += __shfl_xor_sync(0xffffffffu, s, 1);
            q += __shfl_xor_sync(0xffffffffu, q, 1);
            s += __shfl_xor_sync(0xffffffffu, s, 2);
            q += __shfl_xor_sync(0xffffffffu, q, 2);
            int r = rg * 32 + mt * 16 + h * 8 + (lane >> 2);
            if ((lane & 3) == 0) {
                s_red[cg * 128 + r] = s;
                s_red[256 + cg * 128 + r] = q;
            }
        }
    __syncthreads();
#pragma unroll
    for (int mt = 0; mt < 2; mt++)
#pragma unroll
        for (int h = 0; h < 2; h++) {
            int r = rg * 32 + mt * 16 + h * 8 + (lane >> 2);
            float st = s_red[r] + s_red[128 + r];
            float qt = s_red[256 + r] + s_red[384 + r];
            float mu = st * (1.0f / Hdim);
            float inv = rsqrtf(qt * (1.0f / Hdim) - mu * mu + 1e-5f);
            int grow = rowbase + r;
            if (grow < nrows) {
#pragma unroll
                for (int nt = 0; nt < 8; nt++) {
                    int col = cg * 64 + nt * 8 + c2;
                    float2 g = __ldg((const float2*)(gam + col));
                    float2 b = __ldg((const float2*)(bet + col));
                    float2 o;
                    o.x = (vals[mt][h][2 * nt]     - mu) * inv * g.x + b.x;
                    o.y = (vals[mt][h][2 * nt + 1] - mu) * inv * g.y + b.y;
                    size_t base = (size_t)grow * Hdim + col;
                    if (out1) *(float2*)(out1 + base) = o;
                    if (out2) {
                        float2 rv = *(const float2*)(resid + base);
                        *(float2*)(out2 + base) = make_float2(o.x + rv.x, o.y + rv.y);
                    }
                }
            }
        }
}

// smem: s_ah 0, s_al 34816, s_bh 69632, s_bl 104448, s_red 139264 (2048B)
#define SMEM_TOTAL 141312

// ---------------- CellBlock ----------------
__global__ void __launch_bounds__(T, 1) k_cell(
    const float* __restrict__ xin,
    const __nv_bfloat16* __restrict__ w1h, const __nv_bfloat16* __restrict__ w1l,
    const __nv_bfloat16* __restrict__ w2h, const __nv_bfloat16* __restrict__ w2l,
    const __nv_bfloat16* __restrict__ w3h, const __nv_bfloat16* __restrict__ w3l,
    const float* __restrict__ b1, const float* __restrict__ b2, const float* __restrict__ b3,
    const float* __restrict__ gam, const float* __restrict__ bet,
    float* out1, const float* __restrict__ resid, float* out2, int nrows)
{
    extern __shared__ char sm[];
    char* s_ah = sm;
    char* s_al = sm + 34816;
    char* s_bh = sm + 69632;
    char* s_bl = sm + 104448;
    float* s_red = (float*)(sm + 139264);
    int tid = threadIdx.x, w = tid >> 5, lane = tid & 31;
    int rowbase = blockIdx.x * 128;
    uint32_t ah = smem_u32(s_ah), al = smem_u32(s_al);
    uint32_t bh = smem_u32(s_bh), bl = smem_u32(s_bl);
    float acc[2][8][4];

    // layer 1 (K=192 = 128 + 64)
    zero_acc(acc);
    stage_src(xin, Hdim, rowbase, nrows, 128, s_ah, s_al, tid);
    stage_b(w1h, w1l, 192, 0, 128, s_bh, s_bl, tid);
    __syncthreads();
    mma_chunk(ah, al, bh, bl, 8, acc, w, lane);
    __syncthreads();
    stage_src(g_agg, HALF, rowbase, nrows, 64, s_ah, s_al, tid);
    stage_b(w1h, w1l, 192, 128, 64, s_bh, s_bl, tid);
    __syncthreads();
    mma_chunk(ah, al, bh, bl, 4, acc, w, lane);
    __syncthreads();
    epi_act(acc, b1, s_ah, s_al, w, lane);
    // layer 2
    stage_b(w2h, w2l, 128, 0, 128, s_bh, s_bl, tid);
    __syncthreads();
    zero_acc(acc);
    mma_chunk(ah, al, bh, bl, 8, acc, w, lane);
    __syncthreads();
    epi_act(acc, b2, s_ah, s_al, w, lane);
    // layer 3
    stage_b(w3h, w3l, 128, 0, 128, s_bh, s_bl, tid);
    __syncthreads();
    zero_acc(acc);
    mma_chunk(ah, al, bh, bl, 8, acc, w, lane);
    epi_ln(acc, b3, gam, bet, s_red, rowbase, nrows, out1, resid, out2, w, lane);
}

// ---------------- EdgeBlock ----------------
__global__ void __launch_bounds__(T, 1) k_edge(
    const float* __restrict__ ea, const float* __restrict__ xc, const int* __restrict__ ei,
    const __nv_bfloat16* __restrict__ w1h, const __nv_bfloat16* __restrict__ w1l,
    const __nv_bfloat16* __restrict__ w2h, const __nv_bfloat16* __restrict__ w2l,
    const __nv_bfloat16* __restrict__ w3h, const __nv_bfloat16* __restrict__ w3l,
    const float* __restrict__ b1, const float* __restrict__ b2, const float* __restrict__ b3,
    const float* __restrict__ gam, const float* __restrict__ bet,
    float* out2, int E)
{
    extern __shared__ char sm[];
    char* s_ah = sm;
    char* s_al = sm + 34816;
    char* s_bh = sm + 69632;
    char* s_bl = sm + 104448;
    float* s_red = (float*)(sm + 139264);
    int tid = threadIdx.x, w = tid >> 5, lane = tid & 31;
    int rowbase = blockIdx.x * 128;
    uint32_t ah = smem_u32(s_ah), al = smem_u32(s_al);
    uint32_t bh = smem_u32(s_bh), bl = smem_u32(s_bl);
    float acc[2][8][4];

    // layer 1 (K=384 = 3 x 128): [ea | xc[send] | xc[recv]]
    zero_acc(acc);
    stage_src(ea, Hdim, rowbase, E, 128, s_ah, s_al, tid);
    stage_b(w1h, w1l, 384, 0, 128, s_bh, s_bl, tid);
    __syncthreads();
    mma_chunk(ah, al, bh, bl, 8, acc, w, lane);
    __syncthreads();
    stage_gather(xc, ei, rowbase, s_ah, s_al, tid);
    stage_b(w1h, w1l, 384, 128, 128, s_bh, s_bl, tid);
    __syncthreads();
    mma_chunk(ah, al, bh, bl, 8, acc, w, lane);
    __syncthreads();
    stage_gather(xc, ei + E, rowbase, s_ah, s_al, tid);
    stage_b(w1h, w1l, 384, 256, 128, s_bh, s_bl, tid);
    __syncthreads();
    mma_chunk(ah, al, bh, bl, 8, acc, w, lane);
    __syncthreads();
    epi_act(acc, b1, s_ah, s_al, w, lane);
    // layer 2
    stage_b(w2h, w2l, 128, 0, 128, s_bh, s_bl, tid);
    __syncthreads();
    zero_acc(acc);
    mma_chunk(ah, al, bh, bl, 8, acc, w, lane);
    __syncthreads();
    epi_act(acc, b2, s_ah, s_al, w, lane);
    // layer 3
    stage_b(w3h, w3l, 128, 0, 128, s_bh, s_bl, tid);
    __syncthreads();
    zero_acc(acc);
    mma_chunk(ah, al, bh, bl, 8, acc, w, lane);
    epi_ln(acc, b3, gam, bet, s_red, rowbase, E, nullptr, ea, out2, w, lane);
}

// ---------------- host ----------------
extern "C" void kernel_launch(void* const* d_in, const int* in_sizes, int n_in,
                              void* d_out, int out_size)
{
    const float* x     = (const float*)d_in[0];
    const float* ea    = (const float*)d_in[1];
    const float* cb_w1 = (const float*)d_in[2];
    const float* cb_b1 = (const float*)d_in[3];
    const float* cb_w2 = (const float*)d_in[4];
    const float* cb_b2 = (const float*)d_in[5];
    const float* cb_w3 = (const float*)d_in[6];
    const float* cb_b3 = (const float*)d_in[7];
    const float* cb_g  = (const float*)d_in[8];
    const float* cb_be = (const float*)d_in[9];
    const float* eb_w1 = (const float*)d_in[10];
    const float* eb_b1 = (const float*)d_in[11];
    const float* eb_w2 = (const float*)d_in[12];
    const float* eb_b2 = (const float*)d_in[13];
    const float* eb_w3 = (const float*)d_in[14];
    const float* eb_b3 = (const float*)d_in[15];
    const float* eb_g  = (const float*)d_in[16];
    const float* eb_be = (const float*)d_in[17];
    const int*   ei    = (const int*)d_in[18];

    int N = in_sizes[0] / Hdim;
    int E = in_sizes[1] / Hdim;
    float* out_x = (float*)d_out;
    float* out_e = out_x + (size_t)N * Hdim;

    float *xc1, *xc2;
    __nv_bfloat16 *wth, *wtl;
    cudaGetSymbolAddress((void**)&xc1, g_xc1);
    cudaGetSymbolAddress((void**)&xc2, g_xc2);
    cudaGetSymbolAddress((void**)&wth, g_wth);
    cudaGetSymbolAddress((void**)&wtl, g_wtl);

    cudaFuncSetAttribute(k_cell, cudaFuncAttributeMaxDynamicSharedMemorySize, SMEM_TOTAL);
    cudaFuncSetAttribute(k_edge, cudaFuncAttributeMaxDynamicSharedMemorySize, SMEM_TOTAL);

    const int OCB1 = 0, OCB2 = 24576, OCB3 = 40960, OEB1 = 57344, OEB2 = 106496, OEB3 = 122880;
    k_prep<<<(192 * 128 + 255) / 256, 256>>>(cb_w1, 192, OCB1);
    k_prep<<<(128 * 128 + 255) / 256, 256>>>(cb_w2, 128, OCB2);
    k_prep<<<(128 * 128 + 255) / 256, 256>>>(cb_w3, 128, OCB3);
    k_prep<<<(384 * 128 + 255) / 256, 256>>>(eb_w1, 384, OEB1);
    k_prep<<<(128 * 128 + 255) / 256, 256>>>(eb_w2, 128, OEB2);
    k_prep<<<(128 * 128 + 255) / 256, 256>>>(eb_w3, 128, OEB3);

    k_zero<<<(N * HALF + 255) / 256, 256>>>(N * HALF);
    k_scatter<<<(E * 32 + 255) / 256, 256>>>(ea, ei, E);

    int cgrid = (N + 127) / 128;
    int egrid = (E + 127) / 128;

    k_cell<<<cgrid, T, SMEM_TOTAL>>>(x,
        wth + OCB1, wtl + OCB1, wth + OCB2, wtl + OCB2, wth + OCB3, wtl + OCB3,
        cb_b1, cb_b2, cb_b3, cb_g, cb_be, xc1, nullptr, nullptr, N);
    k_cell<<<cgrid, T, SMEM_TOTAL>>>(xc1,
        wth + OCB1, wtl + OCB1, wth + OCB2, wtl + OCB2, wth + OCB3, wtl + OCB3,
        cb_b1, cb_b2, cb_b3, cb_g, cb_be, xc2, x, out_x, N);

    k_edge<<<egrid, T, SMEM_TOTAL>>>(ea, xc2, ei,
        wth + OEB1, wtl + OEB1, wth + OEB2, wtl + OEB2, wth + OEB3, wtl + OEB3,
        eb_b1, eb_b2, eb_b3, eb_g, eb_be, out_e, E);
}

// round 4
// speedup vs baseline: 5.0154x; 2.3348x over previous
#include <cuda_runtime.h>
#include <cstdint>

#define Hdim 128
#define HALF 64
#define NMAX 200000
#define T 256
#define SAF 132            // f32 stride of A tile rows (528B ≡ 16 mod 128 → ldmatrix conflict-free)
#define SBF 36             // f32 stride of B chunk rows (144B ≡ 16 mod 128)
#define SM_B0 67584
#define SM_B1 86016
#define SM_RED 104448
#define SMEM_TOTAL 106496

// ---------------- static device scratch ----------------
__device__ float g_agg[(size_t)NMAX * HALF];
__device__ float g_xc1[(size_t)NMAX * Hdim];
__device__ float g_xc2[(size_t)NMAX * Hdim];
// transposed tf32-rounded weights [n=128][K]
// offsets: cb1(K=192):0  cb2:24576  cb3:40960  eb1(384):57344  eb2:106496  eb3:122880
__device__ float g_wt[139264];

// ---------------- helpers ----------------
__device__ __forceinline__ uint32_t smem_u32(const void* p) {
    uint32_t a;
    asm("{ .reg .u64 t; cvta.to.shared.u64 t, %1; cvt.u32.u64 %0, t; }" : "=r"(a) : "l"(p));
    return a;
}
__device__ __forceinline__ float tf32r(float x) {
    float y; asm("cvt.rna.tf32.f32 %0, %1;" : "=f"(y) : "f"(x)); return y;
}
__device__ __forceinline__ void ldsm4(uint32_t r[4], uint32_t a) {
    asm volatile("ldmatrix.sync.aligned.m8n8.x4.shared.b16 {%0,%1,%2,%3}, [%4];"
        : "=r"(r[0]), "=r"(r[1]), "=r"(r[2]), "=r"(r[3]) : "r"(a));
}
__device__ __forceinline__ void mma8(float d[4], const uint32_t a[4], uint32_t b0, uint32_t b1) {
    asm volatile("mma.sync.aligned.m16n8k8.row.col.f32.tf32.tf32.f32 "
        "{%0,%1,%2,%3}, {%4,%5,%6,%7}, {%8,%9}, {%0,%1,%2,%3};"
        : "+f"(d[0]), "+f"(d[1]), "+f"(d[2]), "+f"(d[3])
        : "r"(a[0]), "r"(a[1]), "r"(a[2]), "r"(a[3]), "r"(b0), "r"(b1));
}
__device__ __forceinline__ float silu_f(float v) {
    return v * (1.0f / (1.0f + __expf(-v)));
}

// ---------------- small kernels ----------------
__global__ void k_zero(int nf4) {
    int i = blockIdx.x * blockDim.x + threadIdx.x;
    if (i < nf4) ((float4*)g_agg)[i] = make_float4(0.f, 0.f, 0.f, 0.f);
}
__global__ void k_scatter(const float* __restrict__ ea, const int* __restrict__ ei, int E) {
    int gid = blockIdx.x * blockDim.x + threadIdx.x;
    int e = gid >> 5;
    if (e >= E) return;
    int c4 = (gid & 31) << 2;
    float4 v = *(const float4*)(ea + (size_t)e * Hdim + c4);
    float* base;
    if (c4 < HALF) { int r = ei[E + e]; base = g_agg + (size_t)r * HALF + c4; }
    else           { int s = ei[e];     base = g_agg + (size_t)s * HALF + (c4 - HALF); }
    asm volatile("red.global.add.v4.f32 [%0], {%1,%2,%3,%4};"
        :: "l"(base), "f"(v.x), "f"(v.y), "f"(v.z), "f"(v.w) : "memory");
}
// all 6 weight transposes fused (also shifts ncu -s 5 capture onto k_edge)
__global__ void k_prep_all(const float* cw1, const float* cw2, const float* cw3,
                           const float* ew1, const float* ew2, const float* ew3) {
    int idx = blockIdx.x * blockDim.x + threadIdx.x;
    if (idx >= 139264) return;
    const float* src; int K, off;
    if      (idx < 24576)  { src = cw1; K = 192; off = 0; }
    else if (idx < 40960)  { src = cw2; K = 128; off = 24576; }
    else if (idx < 57344)  { src = cw3; K = 128; off = 40960; }
    else if (idx < 106496) { src = ew1; K = 384; off = 57344; }
    else if (idx < 122880) { src = ew2; K = 128; off = 106496; }
    else                   { src = ew3; K = 128; off = 122880; }
    int l = idx - off;
    int n = l / K, k = l - n * K;
    g_wt[idx] = tf32r(src[k * Hdim + n]);
}

// ---------------- staging ----------------
__device__ __forceinline__ void stage32(const float* __restrict__ src, int ld,
    int rowbase, int nrows, int ncols, char* sA, int tid)
{
    int nf4 = ncols >> 2;
    int tot = 128 * nf4;
    for (int idx = tid; idx < tot; idx += T) {
        int r = idx / nf4, c4 = (idx % nf4) * 4;
        int grow = rowbase + r; if (grow >= nrows) grow = nrows - 1;
        float4 v = *(const float4*)(src + (size_t)grow * ld + c4);
        v.x = tf32r(v.x); v.y = tf32r(v.y); v.z = tf32r(v.z); v.w = tf32r(v.w);
        *(float4*)(sA + ((size_t)r * SAF + c4) * 4) = v;
    }
}
__device__ __forceinline__ void stage_gather32(const float* __restrict__ xc,
    const int* __restrict__ idxv, int rowbase, char* sA, int tid)
{
    for (int idx = tid; idx < 128 * 32; idx += T) {
        int r = idx >> 5, c4 = (idx & 31) * 4;
        int g = __ldg(idxv + rowbase + r);
        float4 v = *(const float4*)(xc + (size_t)g * Hdim + c4);
        v.x = tf32r(v.x); v.y = tf32r(v.y); v.z = tf32r(v.z); v.w = tf32r(v.w);
        *(float4*)(sA + ((size_t)r * SAF + c4) * 4) = v;
    }
}
// B chunk [128 n-rows x 32 k-cols] via cp.async (double-buffered by caller)
__device__ __forceinline__ void cpa_b(const float* __restrict__ wt, int K, int kb,
                                      uint32_t sb, int tid)
{
#pragma unroll
    for (int i = 0; i < 4; i++) {
        int idx = tid + i * T;
        int n = idx >> 3, c4 = (idx & 7) << 2;
        const float* src = wt + (size_t)n * K + kb + c4;
        uint32_t dst = sb + (uint32_t)(n * SBF + c4) * 4;
        asm volatile("cp.async.cg.shared.global [%0], [%1], 16;" :: "r"(dst), "l"(src) : "memory");
    }
    asm volatile("cp.async.commit_group;" ::: "memory");
}
#define CPA_WAIT() asm volatile("cp.async.wait_group 0;" ::: "memory")

// ---------------- MMA over one 32-col K chunk ----------------
__device__ __forceinline__ void mma_chunk(uint32_t sa_a, uint32_t sbuf_b, float acc[2][8][4]) {
#pragma unroll
    for (int ks = 0; ks < 4; ks++) {
        uint32_t A0[4], A1[4];
        ldsm4(A0, sa_a + ks * 32);
        ldsm4(A1, sa_a + ks * 32 + 16 * SAF * 4);
#pragma unroll
        for (int q = 0; q < 4; q++) {
            uint32_t B[4];
            ldsm4(B, sbuf_b + ks * 32 + q * (16 * SBF * 4));
            mma8(acc[0][2 * q],     A0, B[0], B[2]);
            mma8(acc[1][2 * q],     A1, B[0], B[2]);
            mma8(acc[0][2 * q + 1], A0, B[1], B[3]);
            mma8(acc[1][2 * q + 1], A1, B[1], B[3]);
        }
    }
}
__device__ __forceinline__ void zero_acc(float acc[2][8][4]) {
#pragma unroll
    for (int m = 0; m < 2; m++)
#pragma unroll
        for (int t = 0; t < 8; t++)
#pragma unroll
            for (int i = 0; i < 4; i++) acc[m][t][i] = 0.0f;
}

// ---------------- epilogues ----------------
__device__ __forceinline__ void epi_act(float acc[2][8][4], const float* __restrict__ bias,
                                        char* sA, int w, int lane)
{
    int rg = w & 3, cg = w >> 2, c2 = (lane & 3) * 2, r0 = rg * 32 + (lane >> 2);
#pragma unroll
    for (int mt = 0; mt < 2; mt++)
#pragma unroll
        for (int nt = 0; nt < 8; nt++) {
            int col = cg * 64 + nt * 8 + c2;
            float2 b = __ldg((const float2*)(bias + col));
            int row = r0 + mt * 16;
            float2 o0 = make_float2(tf32r(silu_f(acc[mt][nt][0] + b.x)),
                                    tf32r(silu_f(acc[mt][nt][1] + b.y)));
            *(float2*)(sA + ((size_t)row * SAF + col) * 4) = o0;
            float2 o1 = make_float2(tf32r(silu_f(acc[mt][nt][2] + b.x)),
                                    tf32r(silu_f(acc[mt][nt][3] + b.y)));
            *(float2*)(sA + ((size_t)(row + 8) * SAF + col) * 4) = o1;
        }
}
__device__ __forceinline__ void epi_ln(float acc[2][8][4],
    const float* __restrict__ bias, const float* __restrict__ gam, const float* __restrict__ bet,
    float* s_red, int rowbase, int nrows,
    float* out1, const float* __restrict__ resid, float* out2, int w, int lane)
{
    int rg = w & 3, cg = w >> 2, c2 = (lane & 3) * 2;
    float vals[2][2][16];
#pragma unroll
    for (int mt = 0; mt < 2; mt++)
#pragma unroll
        for (int nt = 0; nt < 8; nt++) {
            int col = cg * 64 + nt * 8 + c2;
            float2 b = __ldg((const float2*)(bias + col));
            vals[mt][0][2 * nt]     = acc[mt][nt][0] + b.x;
            vals[mt][0][2 * nt + 1] = acc[mt][nt][1] + b.y;
            vals[mt][1][2 * nt]     = acc[mt][nt][2] + b.x;
            vals[mt][1][2 * nt + 1] = acc[mt][nt][3] + b.y;
        }
#pragma unroll
    for (int mt = 0; mt < 2; mt++)
#pragma unroll
        for (int h = 0; h < 2; h++) {
            float s = 0.0f, q = 0.0f;
#pragma unroll
            for (int j = 0; j < 16; j++) { float v = vals[mt][h][j]; s += v; q += v * v; }
            s += __shfl_xor_sync(0xffffffffu, s, 1);
            q += __shfl_xor_sync(0xffffffffu, q, 1);
            s += __shfl_xor_sync(0xffffffffu, s, 2);
            q += __shfl_xor_sync(0xffffffffu, q, 2);
            int r = rg * 32 + mt * 16 + h * 8 + (lane >> 2);
            if ((lane & 3) == 0) {
                s_red[cg * 128 + r] = s;
                s_red[256 + cg * 128 + r] = q;
            }
        }
    __syncthreads();
#pragma unroll
    for (int mt = 0; mt < 2; mt++)
#pragma unroll
        for (int h = 0; h < 2; h++) {
            int r = rg * 32 + mt * 16 + h * 8 + (lane >> 2);
            float st = s_red[r] + s_red[128 + r];
            float qt = s_red[256 + r] + s_red[384 + r];
            float mu = st * (1.0f / Hdim);
            float inv = rsqrtf(qt * (1.0f / Hdim) - mu * mu + 1e-5f);
            int grow = rowbase + r;
            if (grow < nrows) {
#pragma unroll
                for (int nt = 0; nt < 8; nt++) {
                    int col = cg * 64 + nt * 8 + c2;
                    float2 g = __ldg((const float2*)(gam + col));
                    float2 b = __ldg((const float2*)(bet + col));
                    float2 o;
                    o.x = (vals[mt][h][2 * nt]     - mu) * inv * g.x + b.x;
                    o.y = (vals[mt][h][2 * nt + 1] - mu) * inv * g.y + b.y;
                    size_t base = (size_t)grow * Hdim + col;
                    if (out1) *(float2*)(out1 + base) = o;
                    if (out2) {
                        float2 rv = *(const float2*)(resid + base);
                        *(float2*)(out2 + base) = make_float2(o.x + rv.x, o.y + rv.y);
                    }
                }
            }
        }
}

// ---------------- CellBlock: [x | agg](192) -> 128 -> 128 -> LN ----------------
__global__ void __launch_bounds__(T, 2) k_cell(
    const float* __restrict__ xin,
    const float* __restrict__ w1, const float* __restrict__ w2, const float* __restrict__ w3,
    const float* __restrict__ b1, const float* __restrict__ b2, const float* __restrict__ b3,
    const float* __restrict__ gam, const float* __restrict__ bet,
    float* out1, const float* __restrict__ resid, float* out2, int nrows)
{
    extern __shared__ char smc[];
    uint32_t sa = smem_u32(smc);
    uint32_t sb[2] = { sa + SM_B0, sa + SM_B1 };
    float* s_red = (float*)(smc + SM_RED);
    int tid = threadIdx.x, w = tid >> 5, lane = tid & 31;
    int rg = w & 3, cg = w >> 2;
    int rowbase = blockIdx.x * 128;
    int arow = (lane & 7) + ((lane >> 3) & 1) * 8;
    int acolf = (lane >> 4) * 4;
    uint32_t a0off = (uint32_t)((rg * 32 + arow) * SAF + acolf) * 4;
    uint32_t boff  = (uint32_t)((cg * 64 + arow) * SBF + acolf) * 4;
    float acc[2][8][4];

    // ---- layer 1 (K = 128 + 64, 6 chunks) ----
    stage32(xin, Hdim, rowbase, nrows, 128, smc, tid);
    cpa_b(w1, 192, 0, sb[0], tid);
    zero_acc(acc);
    for (int c = 0; c < 6; c++) {
        CPA_WAIT();
        __syncthreads();
        if (c == 4) stage32(g_agg, HALF, rowbase, nrows, 64, smc, tid);
        if (c < 5) cpa_b(w1, 192, (c + 1) * 32, sb[(c + 1) & 1], tid);
        if (c == 4) __syncthreads();
        int kc = (c < 4) ? c * 32 : (c - 4) * 32;
        mma_chunk(sa + a0off + (uint32_t)kc * 4, sb[c & 1] + boff, acc);
    }
    __syncthreads();
    cpa_b(w2, 128, 0, sb[0], tid);
    epi_act(acc, b1, smc, w, lane);
    // ---- layer 2 ----
    zero_acc(acc);
    for (int c = 0; c < 4; c++) {
        CPA_WAIT();
        __syncthreads();
        if (c < 3) cpa_b(w2, 128, (c + 1) * 32, sb[(c + 1) & 1], tid);
        mma_chunk(sa + a0off + (uint32_t)(c * 32) * 4, sb[c & 1] + boff, acc);
    }
    __syncthreads();
    cpa_b(w3, 128, 0, sb[0], tid);
    epi_act(acc, b2, smc, w, lane);
    // ---- layer 3 ----
    zero_acc(acc);
    for (int c = 0; c < 4; c++) {
        CPA_WAIT();
        __syncthreads();
        if (c < 3) cpa_b(w3, 128, (c + 1) * 32, sb[(c + 1) & 1], tid);
        mma_chunk(sa + a0off + (uint32_t)(c * 32) * 4, sb[c & 1] + boff, acc);
    }
    epi_ln(acc, b3, gam, bet, s_red, rowbase, nrows, out1, resid, out2, w, lane);
}

// ---------------- EdgeBlock: [ea | xc[s] | xc[r]](384) -> 128 -> 128 -> LN ----------------
__global__ void __launch_bounds__(T, 2) k_edge(
    const float* __restrict__ ea, const float* __restrict__ xc, const int* __restrict__ ei,
    const float* __restrict__ w1, const float* __restrict__ w2, const float* __restrict__ w3,
    const float* __restrict__ b1, const float* __restrict__ b2, const float* __restrict__ b3,
    const float* __restrict__ gam, const float* __restrict__ bet,
    float* out2, int E)
{
    extern __shared__ char smc[];
    uint32_t sa = smem_u32(smc);
    uint32_t sb[2] = { sa + SM_B0, sa + SM_B1 };
    float* s_red = (float*)(smc + SM_RED);
    int tid = threadIdx.x, w = tid >> 5, lane = tid & 31;
    int rg = w & 3, cg = w >> 2;
    int rowbase = blockIdx.x * 128;
    int arow = (lane & 7) + ((lane >> 3) & 1) * 8;
    int acolf = (lane >> 4) * 4;
    uint32_t a0off = (uint32_t)((rg * 32 + arow) * SAF + acolf) * 4;
    uint32_t boff  = (uint32_t)((cg * 64 + arow) * SBF + acolf) * 4;
    float acc[2][8][4];

    // ---- layer 1 (K = 384, 12 chunks, A blocks: ea / xc[send] / xc[recv]) ----
    stage32(ea, Hdim, rowbase, E, 128, smc, tid);
    cpa_b(w1, 384, 0, sb[0], tid);
    zero_acc(acc);
    for (int c = 0; c < 12; c++) {
        CPA_WAIT();
        __syncthreads();
        if (c == 4) stage_gather32(xc, ei, rowbase, smc, tid);
        if (c == 8) stage_gather32(xc, ei + E, rowbase, smc, tid);
        if (c < 11) cpa_b(w1, 384, (c + 1) * 32, sb[(c + 1) & 1], tid);
        if (c == 4 || c == 8) __syncthreads();
        mma_chunk(sa + a0off + (uint32_t)((c & 3) * 32) * 4, sb[c & 1] + boff, acc);
    }
    __syncthreads();
    cpa_b(w2, 128, 0, sb[0], tid);
    epi_act(acc, b1, smc, w, lane);
    // ---- layer 2 ----
    zero_acc(acc);
    for (int c = 0; c < 4; c++) {
        CPA_WAIT();
        __syncthreads();
        if (c < 3) cpa_b(w2, 128, (c + 1) * 32, sb[(c + 1) & 1], tid);
        mma_chunk(sa + a0off + (uint32_t)(c * 32) * 4, sb[c & 1] + boff, acc);
    }
    __syncthreads();
    cpa_b(w3, 128, 0, sb[0], tid);
    epi_act(acc, b2, smc, w, lane);
    // ---- layer 3 ----
    zero_acc(acc);
    for (int c = 0; c < 4; c++) {
        CPA_WAIT();
        __syncthreads();
        if (c < 3) cpa_b(w3, 128, (c + 1) * 32, sb[(c + 1) & 1], tid);
        mma_chunk(sa + a0off + (uint32_t)(c * 32) * 4, sb[c & 1] + boff, acc);
    }
    epi_ln(acc, b3, gam, bet, s_red, rowbase, E, nullptr, ea, out2, w, lane);
}

// ---------------- host ----------------
extern "C" void kernel_launch(void* const* d_in, const int* in_sizes, int n_in,
                              void* d_out, int out_size)
{
    const float* x     = (const float*)d_in[0];
    const float* ea    = (const float*)d_in[1];
    const float* cb_w1 = (const float*)d_in[2];
    const float* cb_b1 = (const float*)d_in[3];
    const float* cb_w2 = (const float*)d_in[4];
    const float* cb_b2 = (const float*)d_in[5];
    const float* cb_w3 = (const float*)d_in[6];
    const float* cb_b3 = (const float*)d_in[7];
    const float* cb_g  = (const float*)d_in[8];
    const float* cb_be = (const float*)d_in[9];
    const float* eb_w1 = (const float*)d_in[10];
    const float* eb_b1 = (const float*)d_in[11];
    const float* eb_w2 = (const float*)d_in[12];
    const float* eb_b2 = (const float*)d_in[13];
    const float* eb_w3 = (const float*)d_in[14];
    const float* eb_b3 = (const float*)d_in[15];
    const float* eb_g  = (const float*)d_in[16];
    const float* eb_be = (const float*)d_in[17];
    const int*   ei    = (const int*)d_in[18];

    int N = in_sizes[0] / Hdim;
    int E = in_sizes[1] / Hdim;
    float* out_x = (float*)d_out;
    float* out_e = out_x + (size_t)N * Hdim;

    float *xc1, *xc2, *wt;
    cudaGetSymbolAddress((void**)&xc1, g_xc1);
    cudaGetSymbolAddress((void**)&xc2, g_xc2);
    cudaGetSymbolAddress((void**)&wt, g_wt);

    cudaFuncSetAttribute(k_cell, cudaFuncAttributeMaxDynamicSharedMemorySize, SMEM_TOTAL);
    cudaFuncSetAttribute(k_edge, cudaFuncAttributeMaxDynamicSharedMemorySize, SMEM_TOTAL);

    const int OCB1 = 0, OCB2 = 24576, OCB3 = 40960, OEB1 = 57344, OEB2 = 106496, OEB3 = 122880;

    k_prep_all<<<(139264 + 255) / 256, 256>>>(cb_w1, cb_w2, cb_w3, eb_w1, eb_w2, eb_w3);
    k_zero<<<(N * HALF / 4 + 255) / 256, 256>>>(N * HALF / 4);
    k_scatter<<<(E * 32 + 255) / 256, 256>>>(ea, ei, E);

    int cgrid = (N + 127) / 128;
    int egrid = (E + 127) / 128;

    k_cell<<<cgrid, T, SMEM_TOTAL>>>(x,   wt + OCB1, wt + OCB2, wt + OCB3,
        cb_b1, cb_b2, cb_b3, cb_g, cb_be, xc1, nullptr, nullptr, N);
    k_cell<<<cgrid, T, SMEM_TOTAL>>>(xc1, wt + OCB1, wt + OCB2, wt + OCB3,
        cb_b1, cb_b2, cb_b3, cb_g, cb_be, xc2, x, out_x, N);

    k_edge<<<egrid, T, SMEM_TOTAL>>>(ea, xc2, ei, wt + OEB1, wt + OEB2, wt + OEB3,
        eb_b1, eb_b2, eb_b3, eb_g, eb_be, out_e, E);
}

// round 5
// speedup vs baseline: 5.0210x; 1.0011x over previous
#include <cuda_runtime.h>
#include <cstdint>

#define Hdim 128
#define HALF 64
#define NMAX 200000
#define T 256
#define SAF 132            // f32 stride of A tile rows (528B ≡ 16 mod 128 → ldmatrix conflict-free)
#define SBF 36             // f32 stride of B chunk rows (144B ≡ 16 mod 128)
#define SM_B0 67584
#define SM_B1 86016
#define SM_RED 104448
#define SMEM_TOTAL 106496

// ---------------- static device scratch ----------------
__device__ float g_agg[(size_t)NMAX * HALF];
__device__ float g_xc1[(size_t)NMAX * Hdim];
__device__ float g_xc2[(size_t)NMAX * Hdim];
// transposed tf32-rounded weights [n=128][K]
// offsets: cb1(K=192):0  cb2:24576  cb3:40960  eb1(384):57344  eb2:106496  eb3:122880
__device__ float g_wt[139264];

// ---------------- helpers ----------------
__device__ __forceinline__ uint32_t smem_u32(const void* p) {
    uint32_t a;
    asm("{ .reg .u64 t; cvta.to.shared.u64 t, %1; cvt.u32.u64 %0, t; }" : "=r"(a) : "l"(p));
    return a;
}
__device__ __forceinline__ float tf32r(float x) {
    float y; asm("cvt.rna.tf32.f32 %0, %1;" : "=f"(y) : "f"(x)); return y;
}
__device__ __forceinline__ void ldsm4(uint32_t r[4], uint32_t a) {
    asm volatile("ldmatrix.sync.aligned.m8n8.x4.shared.b16 {%0,%1,%2,%3}, [%4];"
        : "=r"(r[0]), "=r"(r[1]), "=r"(r[2]), "=r"(r[3]) : "r"(a));
}
__device__ __forceinline__ void mma8(float d[4], const uint32_t a[4], uint32_t b0, uint32_t b1) {
    asm volatile("mma.sync.aligned.m16n8k8.row.col.f32.tf32.tf32.f32 "
        "{%0,%1,%2,%3}, {%4,%5,%6,%7}, {%8,%9}, {%0,%1,%2,%3};"
        : "+f"(d[0]), "+f"(d[1]), "+f"(d[2]), "+f"(d[3])
        : "r"(a[0]), "r"(a[1]), "r"(a[2]), "r"(a[3]), "r"(b0), "r"(b1));
}
__device__ __forceinline__ float silu_f(float v) {
    return v * (1.0f / (1.0f + __expf(-v)));
}

// ---------------- small kernels ----------------
__global__ void k_zero(int nf4) {
    int i = blockIdx.x * blockDim.x + threadIdx.x;
    if (i < nf4) ((float4*)g_agg)[i] = make_float4(0.f, 0.f, 0.f, 0.f);
}
__global__ void k_scatter(const float* __restrict__ ea, const int* __restrict__ ei, int E) {
    int gid = blockIdx.x * blockDim.x + threadIdx.x;
    int e = gid >> 5;
    if (e >= E) return;
    int c4 = (gid & 31) << 2;
    float4 v = *(const float4*)(ea + (size_t)e * Hdim + c4);
    float* base;
    if (c4 < HALF) { int r = ei[E + e]; base = g_agg + (size_t)r * HALF + c4; }
    else           { int s = ei[e];     base = g_agg + (size_t)s * HALF + (c4 - HALF); }
    asm volatile("red.global.add.v4.f32 [%0], {%1,%2,%3,%4};"
        :: "l"(base), "f"(v.x), "f"(v.y), "f"(v.z), "f"(v.w) : "memory");
}
// all 6 weight transposes fused (also shifts ncu -s 5 capture onto k_edge)
__global__ void k_prep_all(const float* cw1, const float* cw2, const float* cw3,
                           const float* ew1, const float* ew2, const float* ew3) {
    int idx = blockIdx.x * blockDim.x + threadIdx.x;
    if (idx >= 139264) return;
    const float* src; int K, off;
    if      (idx < 24576)  { src = cw1; K = 192; off = 0; }
    else if (idx < 40960)  { src = cw2; K = 128; off = 24576; }
    else if (idx < 57344)  { src = cw3; K = 128; off = 40960; }
    else if (idx < 106496) { src = ew1; K = 384; off = 57344; }
    else if (idx < 122880) { src = ew2; K = 128; off = 106496; }
    else                   { src = ew3; K = 128; off = 122880; }
    int l = idx - off;
    int n = l / K, k = l - n * K;
    g_wt[idx] = tf32r(src[k * Hdim + n]);
}

// ---------------- staging ----------------
__device__ __forceinline__ void stage32(const float* __restrict__ src, int ld,
    int rowbase, int nrows, int ncols, char* sA, int tid)
{
    int nf4 = ncols >> 2;
    int tot = 128 * nf4;
    for (int idx = tid; idx < tot; idx += T) {
        int r = idx / nf4, c4 = (idx % nf4) * 4;
        int grow = rowbase + r; if (grow >= nrows) grow = nrows - 1;
        float4 v = *(const float4*)(src + (size_t)grow * ld + c4);
        v.x = tf32r(v.x); v.y = tf32r(v.y); v.z = tf32r(v.z); v.w = tf32r(v.w);
        *(float4*)(sA + ((size_t)r * SAF + c4) * 4) = v;
    }
}
__device__ __forceinline__ void stage_gather32(const float* __restrict__ xc,
    const int* __restrict__ idxv, int rowbase, char* sA, int tid)
{
    for (int idx = tid; idx < 128 * 32; idx += T) {
        int r = idx >> 5, c4 = (idx & 31) * 4;
        int g = __ldg(idxv + rowbase + r);
        float4 v = *(const float4*)(xc + (size_t)g * Hdim + c4);
        v.x = tf32r(v.x); v.y = tf32r(v.y); v.z = tf32r(v.z); v.w = tf32r(v.w);
        *(float4*)(sA + ((size_t)r * SAF + c4) * 4) = v;
    }
}
// B chunk [128 n-rows x 32 k-cols] via cp.async (double-buffered by caller)
__device__ __forceinline__ void cpa_b(const float* __restrict__ wt, int K, int kb,
                                      uint32_t sb, int tid)
{
#pragma unroll
    for (int i = 0; i < 4; i++) {
        int idx = tid + i * T;
        int n = idx >> 3, c4 = (idx & 7) << 2;
        const float* src = wt + (size_t)n * K + kb + c4;
        uint32_t dst = sb + (uint32_t)(n * SBF + c4) * 4;
        asm volatile("cp.async.cg.shared.global [%0], [%1], 16;" :: "r"(dst), "l"(src) : "memory");
    }
    asm volatile("cp.async.commit_group;" ::: "memory");
}
#define CPA_WAIT() asm volatile("cp.async.wait_group 0;" ::: "memory")

// ---------------- MMA over one 32-col K chunk ----------------
__device__ __forceinline__ void mma_chunk(uint32_t sa_a, uint32_t sbuf_b, float acc[2][8][4]) {
#pragma unroll
    for (int ks = 0; ks < 4; ks++) {
        uint32_t A0[4], A1[4];
        ldsm4(A0, sa_a + ks * 32);
        ldsm4(A1, sa_a + ks * 32 + 16 * SAF * 4);
#pragma unroll
        for (int q = 0; q < 4; q++) {
            uint32_t B[4];
            ldsm4(B, sbuf_b + ks * 32 + q * (16 * SBF * 4));
            mma8(acc[0][2 * q],     A0, B[0], B[2]);
            mma8(acc[1][2 * q],     A1, B[0], B[2]);
            mma8(acc[0][2 * q + 1], A0, B[1], B[3]);
            mma8(acc[1][2 * q + 1], A1, B[1], B[3]);
        }
    }
}
__device__ __forceinline__ void zero_acc(float acc[2][8][4]) {
#pragma unroll
    for (int m = 0; m < 2; m++)
#pragma unroll
        for (int t = 0; t < 8; t++)
#pragma unroll
            for (int i = 0; i < 4; i++) acc[m][t][i] = 0.0f;
}

// ---------------- epilogues ----------------
__device__ __forceinline__ void epi_act(float acc[2][8][4], const float* __restrict__ bias,
                                        char* sA, int w, int lane)
{
    int rg = w & 3, cg = w >> 2, c2 = (lane & 3) * 2, r0 = rg * 32 + (lane >> 2);
#pragma unroll
    for (int mt = 0; mt < 2; mt++)
#pragma unroll
        for (int nt = 0; nt < 8; nt++) {
            int col = cg * 64 + nt * 8 + c2;
            float2 b = __ldg((const float2*)(bias + col));
            int row = r0 + mt * 16;
            float2 o0 = make_float2(tf32r(silu_f(acc[mt][nt][0] + b.x)),
                                    tf32r(silu_f(acc[mt][nt][1] + b.y)));
            *(float2*)(sA + ((size_t)row * SAF + col) * 4) = o0;
            float2 o1 = make_float2(tf32r(silu_f(acc[mt][nt][2] + b.x)),
                                    tf32r(silu_f(acc[mt][nt][3] + b.y)));
            *(float2*)(sA + ((size_t)(row + 8) * SAF + col) * 4) = o1;
        }
}
__device__ __forceinline__ void epi_ln(float acc[2][8][4],
    const float* __restrict__ bias, const float* __restrict__ gam, const float* __restrict__ bet,
    float* s_red, int rowbase, int nrows,
    float* out1, const float* __restrict__ resid, float* out2, int w, int lane)
{
    int rg = w & 3, cg = w >> 2, c2 = (lane & 3) * 2;
    float vals[2][2][16];
#pragma unroll
    for (int mt = 0; mt < 2; mt++)
#pragma unroll
        for (int nt = 0; nt < 8; nt++) {
            int col = cg * 64 + nt * 8 + c2;
            float2 b = __ldg((const float2*)(bias + col));
            vals[mt][0][2 * nt]     = acc[mt][nt][0] + b.x;
            vals[mt][0][2 * nt + 1] = acc[mt][nt][1] + b.y;
            vals[mt][1][2 * nt]     = acc[mt][nt][2] + b.x;
            vals[mt][1][2 * nt + 1] = acc[mt][nt][3] + b.y;
        }
#pragma unroll
    for (int mt = 0; mt < 2; mt++)
#pragma unroll
        for (int h = 0; h < 2; h++) {
            float s = 0.0f, q = 0.0f;
#pragma unroll
            for (int j = 0; j < 16; j++) { float v = vals[mt][h][j]; s += v; q += v * v; }
            s += __shfl_xor_sync(0xffffffffu, s, 1);
            q += __shfl_xor_sync(0xffffffffu, q, 1);
            s += __shfl_xor_sync(0xffffffffu, s, 2);
            q += __shfl_xor_sync(0xffffffffu, q, 2);
            int r = rg * 32 + mt * 16 + h * 8 + (lane >> 2);
            if ((lane & 3) == 0) {
                s_red[cg * 128 + r] = s;
                s_red[256 + cg * 128 + r] = q;
            }
        }
    __syncthreads();
#pragma unroll
    for (int mt = 0; mt < 2; mt++)
#pragma unroll
        for (int h = 0; h < 2; h++) {
            int r = rg * 32 + mt * 16 + h * 8 + (lane >> 2);
            float st = s_red[r] + s_red[128 + r];
            float qt = s_red[256 + r] + s_red[384 + r];
            float mu = st * (1.0f / Hdim);
            float inv = rsqrtf(qt * (1.0f / Hdim) - mu * mu + 1e-5f);
            int grow = rowbase + r;
            if (grow < nrows) {
#pragma unroll
                for (int nt = 0; nt < 8; nt++) {
                    int col = cg * 64 + nt * 8 + c2;
                    float2 g = __ldg((const float2*)(gam + col));
                    float2 b = __ldg((const float2*)(bet + col));
                    float2 o;
                    o.x = (vals[mt][h][2 * nt]     - mu) * inv * g.x + b.x;
                    o.y = (vals[mt][h][2 * nt + 1] - mu) * inv * g.y + b.y;
                    size_t base = (size_t)grow * Hdim + col;
                    if (out1) *(float2*)(out1 + base) = o;
                    if (out2) {
                        float2 rv = *(const float2*)(resid + base);
                        *(float2*)(out2 + base) = make_float2(o.x + rv.x, o.y + rv.y);
                    }
                }
            }
        }
}

// ---------------- CellBlock: [x | agg](192) -> 128 -> 128 -> LN ----------------
__global__ void __launch_bounds__(T, 2) k_cell(
    const float* __restrict__ xin,
    const float* __restrict__ w1, const float* __restrict__ w2, const float* __restrict__ w3,
    const float* __restrict__ b1, const float* __restrict__ b2, const float* __restrict__ b3,
    const float* __restrict__ gam, const float* __restrict__ bet,
    float* out1, const float* __restrict__ resid, float* out2, int nrows)
{
    extern __shared__ char smc[];
    uint32_t sa = smem_u32(smc);
    uint32_t sb[2] = { sa + SM_B0, sa + SM_B1 };
    float* s_red = (float*)(smc + SM_RED);
    int tid = threadIdx.x, w = tid >> 5, lane = tid & 31;
    int rg = w & 3, cg = w >> 2;
    int rowbase = blockIdx.x * 128;
    int arow = (lane & 7) + ((lane >> 3) & 1) * 8;
    int acolf = (lane >> 4) * 4;
    uint32_t a0off = (uint32_t)((rg * 32 + arow) * SAF + acolf) * 4;
    uint32_t boff  = (uint32_t)((cg * 64 + arow) * SBF + acolf) * 4;
    float acc[2][8][4];

    // ---- layer 1 (K = 128 + 64, 6 chunks) ----
    stage32(xin, Hdim, rowbase, nrows, 128, smc, tid);
    cpa_b(w1, 192, 0, sb[0], tid);
    zero_acc(acc);
    for (int c = 0; c < 6; c++) {
        CPA_WAIT();
        __syncthreads();
        if (c == 4) stage32(g_agg, HALF, rowbase, nrows, 64, smc, tid);
        if (c < 5) cpa_b(w1, 192, (c + 1) * 32, sb[(c + 1) & 1], tid);
        if (c == 4) __syncthreads();
        int kc = (c < 4) ? c * 32 : (c - 4) * 32;
        mma_chunk(sa + a0off + (uint32_t)kc * 4, sb[c & 1] + boff, acc);
    }
    __syncthreads();
    cpa_b(w2, 128, 0, sb[0], tid);
    epi_act(acc, b1, smc, w, lane);
    // ---- layer 2 ----
    zero_acc(acc);
    for (int c = 0; c < 4; c++) {
        CPA_WAIT();
        __syncthreads();
        if (c < 3) cpa_b(w2, 128, (c + 1) * 32, sb[(c + 1) & 1], tid);
        mma_chunk(sa + a0off + (uint32_t)(c * 32) * 4, sb[c & 1] + boff, acc);
    }
    __syncthreads();
    cpa_b(w3, 128, 0, sb[0], tid);
    epi_act(acc, b2, smc, w, lane);
    // ---- layer 3 ----
    zero_acc(acc);
    for (int c = 0; c < 4; c++) {
        CPA_WAIT();
        __syncthreads();
        if (c < 3) cpa_b(w3, 128, (c + 1) * 32, sb[(c + 1) & 1], tid);
        mma_chunk(sa + a0off + (uint32_t)(c * 32) * 4, sb[c & 1] + boff, acc);
    }
    epi_ln(acc, b3, gam, bet, s_red, rowbase, nrows, out1, resid, out2, w, lane);
}

// ---------------- EdgeBlock: [ea | xc[s] | xc[r]](384) -> 128 -> 128 -> LN ----------------
__global__ void __launch_bounds__(T, 2) k_edge(
    const float* __restrict__ ea, const float* __restrict__ xc, const int* __restrict__ ei,
    const float* __restrict__ w1, const float* __restrict__ w2, const float* __restrict__ w3,
    const float* __restrict__ b1, const float* __restrict__ b2, const float* __restrict__ b3,
    const float* __restrict__ gam, const float* __restrict__ bet,
    float* out2, int E)
{
    extern __shared__ char smc[];
    uint32_t sa = smem_u32(smc);
    uint32_t sb[2] = { sa + SM_B0, sa + SM_B1 };
    float* s_red = (float*)(smc + SM_RED);
    int tid = threadIdx.x, w = tid >> 5, lane = tid & 31;
    int rg = w & 3, cg = w >> 2;
    int rowbase = blockIdx.x * 128;
    int arow = (lane & 7) + ((lane >> 3) & 1) * 8;
    int acolf = (lane >> 4) * 4;
    uint32_t a0off = (uint32_t)((rg * 32 + arow) * SAF + acolf) * 4;
    uint32_t boff  = (uint32_t)((cg * 64 + arow) * SBF + acolf) * 4;
    float acc[2][8][4];

    // ---- layer 1 (K = 384, 12 chunks, A blocks: ea / xc[send] / xc[recv]) ----
    stage32(ea, Hdim, rowbase, E, 128, smc, tid);
    cpa_b(w1, 384, 0, sb[0], tid);
    zero_acc(acc);
    for (int c = 0; c < 12; c++) {
        CPA_WAIT();
        __syncthreads();
        if (c == 4) stage_gather32(xc, ei, rowbase, smc, tid);
        if (c == 8) stage_gather32(xc, ei + E, rowbase, smc, tid);
        if (c < 11) cpa_b(w1, 384, (c + 1) * 32, sb[(c + 1) & 1], tid);
        if (c == 4 || c == 8) __syncthreads();
        mma_chunk(sa + a0off + (uint32_t)((c & 3) * 32) * 4, sb[c & 1] + boff, acc);
    }
    __syncthreads();
    cpa_b(w2, 128, 0, sb[0], tid);
    epi_act(acc, b1, smc, w, lane);
    // ---- layer 2 ----
    zero_acc(acc);
    for (int c = 0; c < 4; c++) {
        CPA_WAIT();
        __syncthreads();
        if (c < 3) cpa_b(w2, 128, (c + 1) * 32, sb[(c + 1) & 1], tid);
        mma_chunk(sa + a0off + (uint32_t)(c * 32) * 4, sb[c & 1] + boff, acc);
    }
    __syncthreads();
    cpa_b(w3, 128, 0, sb[0], tid);
    epi_act(acc, b2, smc, w, lane);
    // ---- layer 3 ----
    zero_acc(acc);
    for (int c = 0; c < 4; c++) {
        CPA_WAIT();
        __syncthreads();
        if (c < 3) cpa_b(w3, 128, (c + 1) * 32, sb[(c + 1) & 1], tid);
        mma_chunk(sa + a0off + (uint32_t)(c * 32) * 4, sb[c & 1] + boff, acc);
    }
    epi_ln(acc, b3, gam, bet, s_red, rowbase, E, nullptr, ea, out2, w, lane);
}

// ---------------- host ----------------
extern "C" void kernel_launch(void* const* d_in, const int* in_sizes, int n_in,
                              void* d_out, int out_size)
{
    const float* x     = (const float*)d_in[0];
    const float* ea    = (const float*)d_in[1];
    const float* cb_w1 = (const float*)d_in[2];
    const float* cb_b1 = (const float*)d_in[3];
    const float* cb_w2 = (const float*)d_in[4];
    const float* cb_b2 = (const float*)d_in[5];
    const float* cb_w3 = (const float*)d_in[6];
    const float* cb_b3 = (const float*)d_in[7];
    const float* cb_g  = (const float*)d_in[8];
    const float* cb_be = (const float*)d_in[9];
    const float* eb_w1 = (const float*)d_in[10];
    const float* eb_b1 = (const float*)d_in[11];
    const float* eb_w2 = (const float*)d_in[12];
    const float* eb_b2 = (const float*)d_in[13];
    const float* eb_w3 = (const float*)d_in[14];
    const float* eb_b3 = (const float*)d_in[15];
    const float* eb_g  = (const float*)d_in[16];
    const float* eb_be = (const float*)d_in[17];
    const int*   ei    = (const int*)d_in[18];

    int N = in_sizes[0] / Hdim;
    int E = in_sizes[1] / Hdim;
    float* out_x = (float*)d_out;
    float* out_e = out_x + (size_t)N * Hdim;

    float *xc1, *xc2, *wt;
    cudaGetSymbolAddress((void**)&xc1, g_xc1);
    cudaGetSymbolAddress((void**)&xc2, g_xc2);
    cudaGetSymbolAddress((void**)&wt, g_wt);

    cudaFuncSetAttribute(k_cell, cudaFuncAttributeMaxDynamicSharedMemorySize, SMEM_TOTAL);
    cudaFuncSetAttribute(k_edge, cudaFuncAttributeMaxDynamicSharedMemorySize, SMEM_TOTAL);

    const int OCB1 = 0, OCB2 = 24576, OCB3 = 40960, OEB1 = 57344, OEB2 = 106496, OEB3 = 122880;

    k_prep_all<<<(139264 + 255) / 256, 256>>>(cb_w1, cb_w2, cb_w3, eb_w1, eb_w2, eb_w3);
    k_zero<<<(N * HALF / 4 + 255) / 256, 256>>>(N * HALF / 4);
    k_scatter<<<(E * 32 + 255) / 256, 256>>>(ea, ei, E);

    int cgrid = (N + 127) / 128;
    int egrid = (E + 127) / 128;

    k_cell<<<cgrid, T, SMEM_TOTAL>>>(x,   wt + OCB1, wt + OCB2, wt + OCB3,
        cb_b1, cb_b2, cb_b3, cb_g, cb_be, xc1, nullptr, nullptr, N);
    k_cell<<<cgrid, T, SMEM_TOTAL>>>(xc1, wt + OCB1, wt + OCB2, wt + OCB3,
        cb_b1, cb_b2, cb_b3, cb_g, cb_be, xc2, x, out_x, N);

    k_edge<<<egrid, T, SMEM_TOTAL>>>(ea, xc2, ei, wt + OEB1, wt + OEB2, wt + OEB3,
        eb_b1, eb_b2, eb_b3, eb_g, eb_be, out_e, E);
}

// round 6
// speedup vs baseline: 6.9425x; 1.3827x over previous
#include <cuda_runtime.h>
#include <cuda_fp16.h>
#include <cstdint>

#define Hdim 128
#define HALF 64
#define NMAX 200000
#define T 256
#define SA 264              // fp16 elems per A row (528B ≡ 16 mod 128: conflict-free ldsm)
#define SB 72               // fp16 elems per B row (144B ≡ 16 mod 128)
#define B0OFF 67584
#define B1OFF 86016
#define REDOFF 104448
#define SMEM_TOTAL 106496

// ---------------- static device scratch ----------------
__device__ float g_agg[(size_t)NMAX * HALF];
__device__ __half g_xc1h[(size_t)NMAX * Hdim];
__device__ __half g_xc2h[(size_t)NMAX * Hdim];
// transposed fp16 weights [n=128][K]; offsets: cb1:0 cb2:24576 cb3:40960 eb1:57344 eb2:106496 eb3:122880
__device__ __half g_wt[139264];

// ---------------- helpers ----------------
__device__ __forceinline__ uint32_t smem_u32(const void* p) {
    uint32_t a;
    asm("{ .reg .u64 t; cvta.to.shared.u64 t, %1; cvt.u32.u64 %0, t; }" : "=r"(a) : "l"(p));
    return a;
}
__device__ __forceinline__ void ldsm4(uint32_t r[4], uint32_t a) {
    asm volatile("ldmatrix.sync.aligned.m8n8.x4.shared.b16 {%0,%1,%2,%3}, [%4];"
        : "=r"(r[0]), "=r"(r[1]), "=r"(r[2]), "=r"(r[3]) : "r"(a));
}
__device__ __forceinline__ void mma16(float d[4], const uint32_t a[4], uint32_t b0, uint32_t b1) {
    asm volatile("mma.sync.aligned.m16n8k16.row.col.f32.f16.f16.f32 "
        "{%0,%1,%2,%3}, {%4,%5,%6,%7}, {%8,%9}, {%0,%1,%2,%3};"
        : "+f"(d[0]), "+f"(d[1]), "+f"(d[2]), "+f"(d[3])
        : "r"(a[0]), "r"(a[1]), "r"(a[2]), "r"(a[3]), "r"(b0), "r"(b1));
}
__device__ __forceinline__ float silu_f(float v) {
    return v * (1.0f / (1.0f + __expf(-v)));
}
#define CPA16(dst, src) asm volatile("cp.async.cg.shared.global [%0], [%1], 16;" :: "r"(dst), "l"(src) : "memory")
#define CPA_COMMIT() asm volatile("cp.async.commit_group;" ::: "memory")
#define CPA_W0() asm volatile("cp.async.wait_group 0;" ::: "memory")
#define CPA_W1() asm volatile("cp.async.wait_group 1;" ::: "memory")

// ---------------- small kernels ----------------
__global__ void k_zero(int nf4) {
    int i = blockIdx.x * blockDim.x + threadIdx.x;
    if (i < nf4) ((float4*)g_agg)[i] = make_float4(0.f, 0.f, 0.f, 0.f);
}
__global__ void k_scatter(const float* __restrict__ ea, const int* __restrict__ ei, int E) {
    int gid = blockIdx.x * blockDim.x + threadIdx.x;
    int e = gid >> 5;
    if (e >= E) return;
    int c4 = (gid & 31) << 2;
    float4 v = *(const float4*)(ea + (size_t)e * Hdim + c4);
    float* base;
    if (c4 < HALF) { int r = ei[E + e]; base = g_agg + (size_t)r * HALF + c4; }
    else           { int s = ei[e];     base = g_agg + (size_t)s * HALF + (c4 - HALF); }
    asm volatile("red.global.add.v4.f32 [%0], {%1,%2,%3,%4};"
        :: "l"(base), "f"(v.x), "f"(v.y), "f"(v.z), "f"(v.w) : "memory");
}
__global__ void k_prep_all(const float* cw1, const float* cw2, const float* cw3,
                           const float* ew1, const float* ew2, const float* ew3) {
    int idx = blockIdx.x * blockDim.x + threadIdx.x;
    if (idx >= 139264) return;
    const float* src; int K, off;
    if      (idx < 24576)  { src = cw1; K = 192; off = 0; }
    else if (idx < 40960)  { src = cw2; K = 128; off = 24576; }
    else if (idx < 57344)  { src = cw3; K = 128; off = 40960; }
    else if (idx < 106496) { src = ew1; K = 384; off = 57344; }
    else if (idx < 122880) { src = ew2; K = 128; off = 106496; }
    else                   { src = ew3; K = 128; off = 122880; }
    int l = idx - off;
    int n = l / K, k = l - n * K;
    g_wt[idx] = __float2half(src[k * Hdim + n]);
}

// ---------------- staging ----------------
// f32 -> fp16 cvt path into A (dcol = dest col offset)
__device__ __forceinline__ void stageF(const float* __restrict__ src, int ld, int ncols,
    int rowbase, int nrows, int dcol, char* smA, int tid)
{
    int nf4 = ncols >> 2;
    for (int idx = tid; idx < 128 * nf4; idx += T) {
        int r = idx / nf4, c4 = (idx % nf4) * 4;
        int grow = rowbase + r; if (grow >= nrows) grow = nrows - 1;
        float4 v = *(const float4*)(src + (size_t)grow * ld + c4);
        half2 h0 = __floats2half2_rn(v.x, v.y);
        half2 h1 = __floats2half2_rn(v.z, v.w);
        uint2 u = make_uint2(*(uint32_t*)&h0, *(uint32_t*)&h1);
        *(uint2*)(smA + ((size_t)(r * SA + dcol + c4)) * 2) = u;
    }
}
// fp16 sequential rows via cp.async
__device__ __forceinline__ void cpaAseq(const __half* __restrict__ src, int rowbase, int nrows,
                                        uint32_t dstbase, int tid) {
#pragma unroll
    for (int i = 0; i < 8; i++) {
        int idx = tid + i * T;
        int r = idx >> 4, c8 = (idx & 15) * 8;
        int grow = rowbase + r; if (grow >= nrows) grow = nrows - 1;
        CPA16(dstbase + (uint32_t)(r * SA + c8) * 2, src + (size_t)grow * Hdim + c8);
    }
    CPA_COMMIT();
}
// fp16 gathered rows via cp.async
__device__ __forceinline__ void cpaGh(const __half* __restrict__ src, const int* __restrict__ eidx,
                                      int rowbase, uint32_t dstbase, int tid) {
#pragma unroll
    for (int i = 0; i < 8; i++) {
        int idx = tid + i * T;
        int r = idx >> 4, c8 = (idx & 15) * 8;
        int srow = __ldg(eidx + rowbase + r);
        CPA16(dstbase + (uint32_t)(r * SA + c8) * 2, src + (size_t)srow * Hdim + c8);
    }
    CPA_COMMIT();
}
// B chunk [128 n x 64 k] fp16 via cp.async
__device__ __forceinline__ void cpaB(const __half* __restrict__ wt, int K, int k0,
                                     uint32_t dstbase, int tid) {
#pragma unroll
    for (int i = 0; i < 4; i++) {
        int idx = tid + i * T;
        int n = idx >> 3, c8 = (idx & 7) * 8;
        CPA16(dstbase + (uint32_t)(n * SB + c8) * 2, wt + (size_t)n * K + k0 + c8);
    }
    CPA_COMMIT();
}

// ---------------- MMA over one 64-col K chunk ----------------
__device__ __forceinline__ void mma_chunk(uint32_t aB, uint32_t bB, float acc[2][8][4]) {
#pragma unroll
    for (int ks = 0; ks < 4; ks++) {
        uint32_t A0[4], A1[4];
        ldsm4(A0, aB + ks * 32);
        ldsm4(A1, aB + ks * 32 + 16 * SA * 2);
#pragma unroll
        for (int q = 0; q < 4; q++) {
            uint32_t B[4];
            ldsm4(B, bB + ks * 32 + q * (16 * SB * 2));
            mma16(acc[0][2 * q],     A0, B[0], B[1]);
            mma16(acc[1][2 * q],     A1, B[0], B[1]);
            mma16(acc[0][2 * q + 1], A0, B[2], B[3]);
            mma16(acc[1][2 * q + 1], A1, B[2], B[3]);
        }
    }
}
__device__ __forceinline__ void zero_acc(float acc[2][8][4]) {
#pragma unroll
    for (int m = 0; m < 2; m++)
#pragma unroll
        for (int t = 0; t < 8; t++)
#pragma unroll
            for (int i = 0; i < 4; i++) acc[m][t][i] = 0.0f;
}

// ---------------- epilogues ----------------
__device__ __forceinline__ void epi_act(float acc[2][8][4], const float* __restrict__ bias,
                                        char* smA, int w, int lane) {
    int rg = w & 3, cg = w >> 2, c2 = (lane & 3) * 2, r0 = rg * 32 + (lane >> 2);
#pragma unroll
    for (int mt = 0; mt < 2; mt++)
#pragma unroll
        for (int nt = 0; nt < 8; nt++) {
            int col = cg * 64 + nt * 8 + c2;
            float2 b = __ldg((const float2*)(bias + col));
            int row = r0 + mt * 16;
            half2 h0 = __floats2half2_rn(silu_f(acc[mt][nt][0] + b.x), silu_f(acc[mt][nt][1] + b.y));
            *(half2*)(smA + ((size_t)(row * SA + col)) * 2) = h0;
            half2 h1 = __floats2half2_rn(silu_f(acc[mt][nt][2] + b.x), silu_f(acc[mt][nt][3] + b.y));
            *(half2*)(smA + ((size_t)((row + 8) * SA + col)) * 2) = h1;
        }
}
__device__ __forceinline__ void epi_ln(float acc[2][8][4],
    const float* __restrict__ bias, const float* __restrict__ gam, const float* __restrict__ bet,
    float* s_red, int rowbase, int nrows,
    __half* out1h, const float* __restrict__ resid, float* out2, int w, int lane)
{
    int rg = w & 3, cg = w >> 2, c2 = (lane & 3) * 2;
    float vals[2][2][16];
#pragma unroll
    for (int mt = 0; mt < 2; mt++)
#pragma unroll
        for (int nt = 0; nt < 8; nt++) {
            int col = cg * 64 + nt * 8 + c2;
            float2 b = __ldg((const float2*)(bias + col));
            vals[mt][0][2 * nt]     = acc[mt][nt][0] + b.x;
            vals[mt][0][2 * nt + 1] = acc[mt][nt][1] + b.y;
            vals[mt][1][2 * nt]     = acc[mt][nt][2] + b.x;
            vals[mt][1][2 * nt + 1] = acc[mt][nt][3] + b.y;
        }
#pragma unroll
    for (int mt = 0; mt < 2; mt++)
#pragma unroll
        for (int h = 0; h < 2; h++) {
            float s = 0.0f, q = 0.0f;
#pragma unroll
            for (int j = 0; j < 16; j++) { float v = vals[mt][h][j]; s += v; q += v * v; }
            s += __shfl_xor_sync(0xffffffffu, s, 1);
            q += __shfl_xor_sync(0xffffffffu, q, 1);
            s += __shfl_xor_sync(0xffffffffu, s, 2);
            q += __shfl_xor_sync(0xffffffffu, q, 2);
            int r = rg * 32 + mt * 16 + h * 8 + (lane >> 2);
            if ((lane & 3) == 0) {
                s_red[cg * 128 + r] = s;
                s_red[256 + cg * 128 + r] = q;
            }
        }
    __syncthreads();
#pragma unroll
    for (int mt = 0; mt < 2; mt++)
#pragma unroll
        for (int h = 0; h < 2; h++) {
            int r = rg * 32 + mt * 16 + h * 8 + (lane >> 2);
            float st = s_red[r] + s_red[128 + r];
            float qt = s_red[256 + r] + s_red[384 + r];
            float mu = st * (1.0f / Hdim);
            float inv = rsqrtf(qt * (1.0f / Hdim) - mu * mu + 1e-5f);
            int grow = rowbase + r;
            if (grow < nrows) {
#pragma unroll
                for (int nt = 0; nt < 8; nt++) {
                    int col = cg * 64 + nt * 8 + c2;
                    float2 g = __ldg((const float2*)(gam + col));
                    float2 b = __ldg((const float2*)(bet + col));
                    float2 o;
                    o.x = (vals[mt][h][2 * nt]     - mu) * inv * g.x + b.x;
                    o.y = (vals[mt][h][2 * nt + 1] - mu) * inv * g.y + b.y;
                    size_t base = (size_t)grow * Hdim + col;
                    if (out1h) *(half2*)(out1h + base) = __floats2half2_rn(o.x, o.y);
                    if (out2) {
                        float2 rv = *(const float2*)(resid + base);
                        *(float2*)(out2 + base) = make_float2(o.x + rv.x, o.y + rv.y);
                    }
                }
            }
        }
}

// ---------------- CellBlock: [x | agg](192) -> 128 -> 128 -> LN ----------------
__global__ void __launch_bounds__(T, 2) k_cell(
    const float* __restrict__ xin32, const __half* __restrict__ xin16,
    const __half* __restrict__ w1, const __half* __restrict__ w2, const __half* __restrict__ w3,
    const float* __restrict__ b1, const float* __restrict__ b2, const float* __restrict__ b3,
    const float* __restrict__ gam, const float* __restrict__ bet,
    __half* out1h, const float* __restrict__ resid, float* out2, int nrows)
{
    extern __shared__ char smc[];
    uint32_t sa = smem_u32(smc);
    uint32_t sbB[2] = { sa + B0OFF, sa + B1OFF };
    float* s_red = (float*)(smc + REDOFF);
    int tid = threadIdx.x, w = tid >> 5, lane = tid & 31;
    int rg = w & 3, cg = w >> 2;
    int rowbase = blockIdx.x * 128;
    int arow = (lane & 7) + ((lane >> 3) & 1) * 8;
    int acol = (lane >> 4) * 8;
    int b_r = (lane & 7) + (lane >> 4) * 8;
    int b_c = ((lane >> 3) & 1) * 8;
    uint32_t aW = sa + (uint32_t)((rg * 32 + arow) * SA + acol) * 2;
    uint32_t bo = (uint32_t)((cg * 64 + b_r) * SB + b_c) * 2;
    float acc[2][8][4];

    // stage A layer1: [xin(128) | agg(64)]
    if (xin16) cpaAseq(xin16, rowbase, nrows, sa, tid);
    else       stageF(xin32, Hdim, 128, rowbase, nrows, 0, smc, tid);
    stageF(g_agg, HALF, 64, rowbase, nrows, 128, smc, tid);
    cpaB(w1, 192, 0, sbB[0], tid);
    zero_acc(acc);
    // layer1: 3 chunks (bufs 0,1,0)
    for (int c = 0; c < 3; c++) {
        CPA_W0(); __syncthreads();
        if (c < 2) cpaB(w1, 192, (c + 1) * 64, sbB[(c + 1) & 1], tid);
        mma_chunk(aW + (uint32_t)(c * 64) * 2, sbB[c & 1] + bo, acc);
    }
    __syncthreads();
    cpaB(w2, 128, 0, sbB[1], tid);
    epi_act(acc, b1, smc, w, lane);
    // layer2: bufs 1,0
    zero_acc(acc);
    for (int c = 0; c < 2; c++) {
        CPA_W0(); __syncthreads();
        if (c < 1) cpaB(w2, 128, 64, sbB[0], tid);
        mma_chunk(aW + (uint32_t)(c * 64) * 2, sbB[(c + 1) & 1] + bo, acc);
    }
    __syncthreads();
    cpaB(w3, 128, 0, sbB[1], tid);
    epi_act(acc, b2, smc, w, lane);
    // layer3: bufs 1,0
    zero_acc(acc);
    for (int c = 0; c < 2; c++) {
        CPA_W0(); __syncthreads();
        if (c < 1) cpaB(w3, 128, 64, sbB[0], tid);
        mma_chunk(aW + (uint32_t)(c * 64) * 2, sbB[(c + 1) & 1] + bo, acc);
    }
    epi_ln(acc, b3, gam, bet, s_red, rowbase, nrows, out1h, resid, out2, w, lane);
}

// ---------------- EdgeBlock: [ea | xc[s] | xc[r]](384) -> 128 -> 128 -> LN ----------------
__global__ void __launch_bounds__(T, 2) k_edge(
    const float* __restrict__ ea, const __half* __restrict__ xch, const int* __restrict__ ei,
    const __half* __restrict__ w1, const __half* __restrict__ w2, const __half* __restrict__ w3,
    const float* __restrict__ b1, const float* __restrict__ b2, const float* __restrict__ b3,
    const float* __restrict__ gam, const float* __restrict__ bet,
    float* out2, int E)
{
    extern __shared__ char smc[];
    uint32_t sa = smem_u32(smc);
    uint32_t sbB[2] = { sa + B0OFF, sa + B1OFF };
    float* s_red = (float*)(smc + REDOFF);
    int tid = threadIdx.x, w = tid >> 5, lane = tid & 31;
    int rg = w & 3, cg = w >> 2;
    int rowbase = blockIdx.x * 128;
    int arow = (lane & 7) + ((lane >> 3) & 1) * 8;
    int acol = (lane >> 4) * 8;
    int b_r = (lane & 7) + (lane >> 4) * 8;
    int b_c = ((lane >> 3) & 1) * 8;
    uint32_t aW = sa + (uint32_t)((rg * 32 + arow) * SA + acol) * 2;
    uint32_t bo = (uint32_t)((cg * 64 + b_r) * SB + b_c) * 2;
    float acc[2][8][4];

    // layer1: K=384, 6 chunks; A segments ping-pong: seg0(ea)->A0, seg1(xc[s])->A1, seg2(xc[r])->A0
    stageF(ea, Hdim, 128, rowbase, E, 0, smc, tid);
    cpaB(w1, 384, 0, sbB[0], tid);
    zero_acc(acc);
    for (int c = 0; c < 6; c++) {
        if (c == 1 || c == 3) { CPA_W1(); } else { CPA_W0(); }
        __syncthreads();
        if (c < 5) cpaB(w1, 384, (c + 1) * 64, sbB[(c + 1) & 1], tid);
        if (c == 0) cpaGh(xch, ei,     rowbase, sa + 128u * 2, tid);   // seg1 -> A cols 128-255
        if (c == 2) cpaGh(xch, ei + E, rowbase, sa, tid);              // seg2 -> A cols 0-127
        uint32_t aoff = (uint32_t)((((c >> 1) & 1) * 128) + (c & 1) * 64) * 2;
        mma_chunk(aW + aoff, sbB[c & 1] + bo, acc);
    }
    __syncthreads();
    cpaB(w2, 128, 0, sbB[0], tid);
    epi_act(acc, b1, smc, w, lane);
    // layer2: bufs 0,1
    zero_acc(acc);
    for (int c = 0; c < 2; c++) {
        CPA_W0(); __syncthreads();
        if (c < 1) cpaB(w2, 128, 64, sbB[1], tid);
        mma_chunk(aW + (uint32_t)(c * 64) * 2, sbB[c & 1] + bo, acc);
    }
    __syncthreads();
    cpaB(w3, 128, 0, sbB[0], tid);
    epi_act(acc, b2, smc, w, lane);
    // layer3: bufs 0,1
    zero_acc(acc);
    for (int c = 0; c < 2; c++) {
        CPA_W0(); __syncthreads();
        if (c < 1) cpaB(w3, 128, 64, sbB[1], tid);
        mma_chunk(aW + (uint32_t)(c * 64) * 2, sbB[c & 1] + bo, acc);
    }
    epi_ln(acc, b3, gam, bet, s_red, rowbase, E, nullptr, ea, out2, w, lane);
}

// ---------------- host ----------------
extern "C" void kernel_launch(void* const* d_in, const int* in_sizes, int n_in,
                              void* d_out, int out_size)
{
    const float* x     = (const float*)d_in[0];
    const float* ea    = (const float*)d_in[1];
    const float* cb_w1 = (const float*)d_in[2];
    const float* cb_b1 = (const float*)d_in[3];
    const float* cb_w2 = (const float*)d_in[4];
    const float* cb_b2 = (const float*)d_in[5];
    const float* cb_w3 = (const float*)d_in[6];
    const float* cb_b3 = (const float*)d_in[7];
    const float* cb_g  = (const float*)d_in[8];
    const float* cb_be = (const float*)d_in[9];
    const float* eb_w1 = (const float*)d_in[10];
    const float* eb_b1 = (const float*)d_in[11];
    const float* eb_w2 = (const float*)d_in[12];
    const float* eb_b2 = (const float*)d_in[13];
    const float* eb_w3 = (const float*)d_in[14];
    const float* eb_b3 = (const float*)d_in[15];
    const float* eb_g  = (const float*)d_in[16];
    const float* eb_be = (const float*)d_in[17];
    const int*   ei    = (const int*)d_in[18];

    int N = in_sizes[0] / Hdim;
    int E = in_sizes[1] / Hdim;
    float* out_x = (float*)d_out;
    float* out_e = out_x + (size_t)N * Hdim;

    __half *xc1h, *xc2h, *wt;
    cudaGetSymbolAddress((void**)&xc1h, g_xc1h);
    cudaGetSymbolAddress((void**)&xc2h, g_xc2h);
    cudaGetSymbolAddress((void**)&wt, g_wt);

    cudaFuncSetAttribute(k_cell, cudaFuncAttributeMaxDynamicSharedMemorySize, SMEM_TOTAL);
    cudaFuncSetAttribute(k_edge, cudaFuncAttributeMaxDynamicSharedMemorySize, SMEM_TOTAL);

    const int OCB1 = 0, OCB2 = 24576, OCB3 = 40960, OEB1 = 57344, OEB2 = 106496, OEB3 = 122880;

    k_prep_all<<<(139264 + 255) / 256, 256>>>(cb_w1, cb_w2, cb_w3, eb_w1, eb_w2, eb_w3);
    k_zero<<<(N * HALF / 4 + 255) / 256, 256>>>(N * HALF / 4);
    k_scatter<<<(E * 32 + 255) / 256, 256>>>(ea, ei, E);

    int cgrid = (N + 127) / 128;
    int egrid = (E + 127) / 128;

    k_cell<<<cgrid, T, SMEM_TOTAL>>>(x, nullptr, wt + OCB1, wt + OCB2, wt + OCB3,
        cb_b1, cb_b2, cb_b3, cb_g, cb_be, xc1h, nullptr, nullptr, N);
    k_cell<<<cgrid, T, SMEM_TOTAL>>>(nullptr, xc1h, wt + OCB1, wt + OCB2, wt + OCB3,
        cb_b1, cb_b2, cb_b3, cb_g, cb_be, xc2h, x, out_x, N);

    k_edge<<<egrid, T, SMEM_TOTAL>>>(ea, xc2h, ei, wt + OEB1, wt + OEB2, wt + OEB3,
        eb_b1, eb_b2, eb_b3, eb_g, eb_be, out_e, E);
}

// round 7
// speedup vs baseline: 7.1389x; 1.0283x over previous
#include <cuda_runtime.h>
#include <cuda_fp16.h>
#include <cstdint>

#define Hdim 128
#define HALF 64
#define NMAX 200000
#define EMAX 400000
#define T 128
#define SAc 200             // cell A stride (fp16 elems): 400B ≡ 16 mod 128
#define SAe 264             // edge A stride: 528B ≡ 16 mod 128
#define SB 72               // B stride: 144B ≡ 16 mod 128
// cell smem: A 0..25600, B0 25600, B1 44032, red 62464..63488
#define C_B0 25600
#define C_B1 44032
#define C_RED 62464
#define SMEM_CELL 63488
// edge smem: A 0..33792, B0 33792, B1 52224, red 70656..71680
#define E_B0 33792
#define E_B1 52224
#define E_RED 70656
#define SMEM_EDGE 71680

// ---------------- static device scratch ----------------
__device__ float  g_agg[(size_t)NMAX * HALF];
__device__ __half g_aggh[(size_t)NMAX * HALF];
__device__ __half g_xh[(size_t)NMAX * Hdim];
__device__ __half g_xc1h[(size_t)NMAX * Hdim];
__device__ __half g_xc2h[(size_t)NMAX * Hdim];
__device__ __half g_eah[(size_t)EMAX * Hdim];
// transposed fp16 weights [n=128][K]; offsets: cb1:0 cb2:24576 cb3:40960 eb1:57344 eb2:106496 eb3:122880
__device__ __half g_wt[139264];

// ---------------- helpers ----------------
__device__ __forceinline__ uint32_t smem_u32(const void* p) {
    uint32_t a;
    asm("{ .reg .u64 t; cvta.to.shared.u64 t, %1; cvt.u32.u64 %0, t; }" : "=r"(a) : "l"(p));
    return a;
}
__device__ __forceinline__ void ldsm4(uint32_t r[4], uint32_t a) {
    asm volatile("ldmatrix.sync.aligned.m8n8.x4.shared.b16 {%0,%1,%2,%3}, [%4];"
        : "=r"(r[0]), "=r"(r[1]), "=r"(r[2]), "=r"(r[3]) : "r"(a));
}
__device__ __forceinline__ void mma16(float d[4], const uint32_t a[4], uint32_t b0, uint32_t b1) {
    asm volatile("mma.sync.aligned.m16n8k16.row.col.f32.f16.f16.f32 "
        "{%0,%1,%2,%3}, {%4,%5,%6,%7}, {%8,%9}, {%0,%1,%2,%3};"
        : "+f"(d[0]), "+f"(d[1]), "+f"(d[2]), "+f"(d[3])
        : "r"(a[0]), "r"(a[1]), "r"(a[2]), "r"(a[3]), "r"(b0), "r"(b1));
}
__device__ __forceinline__ float silu_f(float v) {
    return v * (1.0f / (1.0f + __expf(-v)));
}
#define CPA16(dst, src) asm volatile("cp.async.cg.shared.global [%0], [%1], 16;" :: "r"(dst), "l"(src) : "memory")
#define CPA_COMMIT() asm volatile("cp.async.commit_group;" ::: "memory")
#define CPA_W0() asm volatile("cp.async.wait_group 0;" ::: "memory")
#define CPA_W1() asm volatile("cp.async.wait_group 1;" ::: "memory")

// ---------------- small kernels ----------------
__global__ void k_zero(int nf4) {
    int i = blockIdx.x * blockDim.x + threadIdx.x;
    if (i < nf4) ((float4*)g_agg)[i] = make_float4(0.f, 0.f, 0.f, 0.f);
}
// fp32 -> fp16 bulk convert
__global__ void k_cvt(const float* __restrict__ src, __half* __restrict__ dst, int n4) {
    int i = blockIdx.x * blockDim.x + threadIdx.x;
    if (i >= n4) return;
    float4 v = ((const float4*)src)[i];
    half2 h0 = __floats2half2_rn(v.x, v.y);
    half2 h1 = __floats2half2_rn(v.z, v.w);
    *(uint2*)(dst + (size_t)i * 4) = make_uint2(*(uint32_t*)&h0, *(uint32_t*)&h1);
}
// scatter + fused ea->fp16 conversion
__global__ void k_scatter(const float* __restrict__ ea, const int* __restrict__ ei, int E) {
    int gid = blockIdx.x * blockDim.x + threadIdx.x;
    int e = gid >> 5;
    if (e >= E) return;
    int c4 = (gid & 31) << 2;
    float4 v = *(const float4*)(ea + (size_t)e * Hdim + c4);
    half2 h0 = __floats2half2_rn(v.x, v.y);
    half2 h1 = __floats2half2_rn(v.z, v.w);
    *(uint2*)(g_eah + (size_t)e * Hdim + c4) = make_uint2(*(uint32_t*)&h0, *(uint32_t*)&h1);
    float* base;
    if (c4 < HALF) { int r = ei[E + e]; base = g_agg + (size_t)r * HALF + c4; }
    else           { int s = ei[e];     base = g_agg + (size_t)s * HALF + (c4 - HALF); }
    asm volatile("red.global.add.v4.f32 [%0], {%1,%2,%3,%4};"
        :: "l"(base), "f"(v.x), "f"(v.y), "f"(v.z), "f"(v.w) : "memory");
}
__global__ void k_prep_all(const float* cw1, const float* cw2, const float* cw3,
                           const float* ew1, const float* ew2, const float* ew3) {
    int idx = blockIdx.x * blockDim.x + threadIdx.x;
    if (idx >= 139264) return;
    const float* src; int K, off;
    if      (idx < 24576)  { src = cw1; K = 192; off = 0; }
    else if (idx < 40960)  { src = cw2; K = 128; off = 24576; }
    else if (idx < 57344)  { src = cw3; K = 128; off = 40960; }
    else if (idx < 106496) { src = ew1; K = 384; off = 57344; }
    else if (idx < 122880) { src = ew2; K = 128; off = 106496; }
    else                   { src = ew3; K = 128; off = 122880; }
    int l = idx - off;
    int n = l / K, k = l - n * K;
    g_wt[idx] = __float2half(src[k * Hdim + n]);
}

// ---------------- async staging (64-row tiles, 128 threads) ----------------
__device__ __forceinline__ void cpaH(const __half* __restrict__ src, int ld, int ncol8,
                                     int rowbase, int nrows, uint32_t dstbase, int strideH, int tid) {
    int tot = 64 * ncol8;
    for (int idx = tid; idx < tot; idx += T) {
        int r = idx / ncol8, c8 = (idx - r * ncol8) * 8;
        int grow = rowbase + r; if (grow >= nrows) grow = nrows - 1;
        CPA16(dstbase + (uint32_t)(r * strideH + c8) * 2, src + (size_t)grow * ld + c8);
    }
    CPA_COMMIT();
}
__device__ __forceinline__ void cpaGh(const __half* __restrict__ src, const int* __restrict__ eidx,
                                      int rowbase, uint32_t dstbase, int strideH, int tid) {
#pragma unroll
    for (int i = 0; i < 8; i++) {
        int idx = tid + i * T;
        int r = idx >> 4, c8 = (idx & 15) * 8;
        int srow = __ldg(eidx + rowbase + r);
        CPA16(dstbase + (uint32_t)(r * strideH + c8) * 2, src + (size_t)srow * Hdim + c8);
    }
    CPA_COMMIT();
}
__device__ __forceinline__ void cpaB(const __half* __restrict__ wt, int K, int k0,
                                     uint32_t dstbase, int tid) {
#pragma unroll
    for (int i = 0; i < 8; i++) {
        int idx = tid + i * T;
        int n = idx >> 3, c8 = (idx & 7) * 8;
        CPA16(dstbase + (uint32_t)(n * SB + c8) * 2, wt + (size_t)n * K + k0 + c8);
    }
    CPA_COMMIT();
}

// ---------------- MMA over one 64-col K chunk (warp: 32 rows x 64 cols) ----------------
__device__ __forceinline__ void mma_chunk(uint32_t aB, uint32_t bB, float acc[2][8][4], int saStrideB) {
#pragma unroll
    for (int ks = 0; ks < 4; ks++) {
        uint32_t A0[4], A1[4];
        ldsm4(A0, aB + ks * 32);
        ldsm4(A1, aB + ks * 32 + 16 * saStrideB);
#pragma unroll
        for (int q = 0; q < 4; q++) {
            uint32_t B[4];
            ldsm4(B, bB + ks * 32 + q * (16 * SB * 2));
            mma16(acc[0][2 * q],     A0, B[0], B[1]);
            mma16(acc[1][2 * q],     A1, B[0], B[1]);
            mma16(acc[0][2 * q + 1], A0, B[2], B[3]);
            mma16(acc[1][2 * q + 1], A1, B[2], B[3]);
        }
    }
}
__device__ __forceinline__ void zero_acc(float acc[2][8][4]) {
#pragma unroll
    for (int m = 0; m < 2; m++)
#pragma unroll
        for (int t = 0; t < 8; t++)
#pragma unroll
            for (int i = 0; i < 4; i++) acc[m][t][i] = 0.0f;
}

// ---------------- epilogues (4 warps: rg = w&1, cg = w>>1) ----------------
__device__ __forceinline__ void epi_act(float acc[2][8][4], const float* __restrict__ bias,
                                        char* smA, int strideH, int w, int lane) {
    int rg = w & 1, cg = w >> 1, c2 = (lane & 3) * 2, r0 = rg * 32 + (lane >> 2);
#pragma unroll
    for (int mt = 0; mt < 2; mt++)
#pragma unroll
        for (int nt = 0; nt < 8; nt++) {
            int col = cg * 64 + nt * 8 + c2;
            float2 b = __ldg((const float2*)(bias + col));
            int row = r0 + mt * 16;
            half2 h0 = __floats2half2_rn(silu_f(acc[mt][nt][0] + b.x), silu_f(acc[mt][nt][1] + b.y));
            *(half2*)(smA + ((size_t)(row * strideH + col)) * 2) = h0;
            half2 h1 = __floats2half2_rn(silu_f(acc[mt][nt][2] + b.x), silu_f(acc[mt][nt][3] + b.y));
            *(half2*)(smA + ((size_t)((row + 8) * strideH + col)) * 2) = h1;
        }
}
__device__ __forceinline__ void epi_ln(float acc[2][8][4],
    const float* __restrict__ bias, const float* __restrict__ gam, const float* __restrict__ bet,
    float* s_red, int rowbase, int nrows,
    __half* out1h, const float* __restrict__ resid, float* out2, int w, int lane)
{
    int rg = w & 1, cg = w >> 1, c2 = (lane & 3) * 2;
    float vals[2][2][16];
#pragma unroll
    for (int mt = 0; mt < 2; mt++)
#pragma unroll
        for (int nt = 0; nt < 8; nt++) {
            int col = cg * 64 + nt * 8 + c2;
            float2 b = __ldg((const float2*)(bias + col));
            vals[mt][0][2 * nt]     = acc[mt][nt][0] + b.x;
            vals[mt][0][2 * nt + 1] = acc[mt][nt][1] + b.y;
            vals[mt][1][2 * nt]     = acc[mt][nt][2] + b.x;
            vals[mt][1][2 * nt + 1] = acc[mt][nt][3] + b.y;
        }
#pragma unroll
    for (int mt = 0; mt < 2; mt++)
#pragma unroll
        for (int h = 0; h < 2; h++) {
            float s = 0.0f, q = 0.0f;
#pragma unroll
            for (int j = 0; j < 16; j++) { float v = vals[mt][h][j]; s += v; q += v * v; }
            s += __shfl_xor_sync(0xffffffffu, s, 1);
            q += __shfl_xor_sync(0xffffffffu, q, 1);
            s += __shfl_xor_sync(0xffffffffu, s, 2);
            q += __shfl_xor_sync(0xffffffffu, q, 2);
            int r = rg * 32 + mt * 16 + h * 8 + (lane >> 2);
            if ((lane & 3) == 0) {
                s_red[cg * 64 + r] = s;
                s_red[128 + cg * 64 + r] = q;
            }
        }
    __syncthreads();
#pragma unroll
    for (int mt = 0; mt < 2; mt++)
#pragma unroll
        for (int h = 0; h < 2; h++) {
            int r = rg * 32 + mt * 16 + h * 8 + (lane >> 2);
            float st = s_red[r] + s_red[64 + r];
            float qt = s_red[128 + r] + s_red[192 + r];
            float mu = st * (1.0f / Hdim);
            float inv = rsqrtf(qt * (1.0f / Hdim) - mu * mu + 1e-5f);
            int grow = rowbase + r;
            if (grow < nrows) {
#pragma unroll
                for (int nt = 0; nt < 8; nt++) {
                    int col = cg * 64 + nt * 8 + c2;
                    float2 g = __ldg((const float2*)(gam + col));
                    float2 b = __ldg((const float2*)(bet + col));
                    float2 o;
                    o.x = (vals[mt][h][2 * nt]     - mu) * inv * g.x + b.x;
                    o.y = (vals[mt][h][2 * nt + 1] - mu) * inv * g.y + b.y;
                    size_t base = (size_t)grow * Hdim + col;
                    if (out1h) *(half2*)(out1h + base) = __floats2half2_rn(o.x, o.y);
                    if (out2) {
                        float2 rv = *(const float2*)(resid + base);
                        *(float2*)(out2 + base) = make_float2(o.x + rv.x, o.y + rv.y);
                    }
                }
            }
        }
}

// ---------------- CellBlock: [x | agg](192) -> 128 -> 128 -> LN ----------------
__global__ void __launch_bounds__(T, 3) k_cell(
    const __half* __restrict__ xin, const __half* __restrict__ aggh,
    const __half* __restrict__ w1, const __half* __restrict__ w2, const __half* __restrict__ w3,
    const float* __restrict__ b1, const float* __restrict__ b2, const float* __restrict__ b3,
    const float* __restrict__ gam, const float* __restrict__ bet,
    __half* out1h, const float* __restrict__ resid, float* out2, int nrows)
{
    extern __shared__ char smc[];
    uint32_t sa = smem_u32(smc);
    uint32_t sbB[2] = { sa + C_B0, sa + C_B1 };
    float* s_red = (float*)(smc + C_RED);
    int tid = threadIdx.x, w = tid >> 5, lane = tid & 31;
    int rg = w & 1, cg = w >> 1;
    int rowbase = blockIdx.x * 64;
    int arow = (lane & 7) + ((lane >> 3) & 1) * 8;
    int acol = (lane >> 4) * 8;
    int b_r = (lane & 7) + (lane >> 4) * 8;
    int b_c = ((lane >> 3) & 1) * 8;
    uint32_t aW = sa + (uint32_t)((rg * 32 + arow) * SAc + acol) * 2;
    uint32_t bo = (uint32_t)((cg * 64 + b_r) * SB + b_c) * 2;
    float acc[2][8][4];

    cpaH(xin, Hdim, 16, rowbase, nrows, sa, SAc, tid);
    cpaH(aggh, HALF, 8, rowbase, nrows, sa + 128u * 2, SAc, tid);
    cpaB(w1, 192, 0, sbB[0], tid);
    zero_acc(acc);
    // layer1: 3 chunks (bufs 0,1,0)
    for (int c = 0; c < 3; c++) {
        CPA_W0(); __syncthreads();
        if (c < 2) cpaB(w1, 192, (c + 1) * 64, sbB[(c + 1) & 1], tid);
        mma_chunk(aW + (uint32_t)(c * 64) * 2, sbB[c & 1] + bo, acc, SAc * 2);
    }
    __syncthreads();
    cpaB(w2, 128, 0, sbB[1], tid);
    epi_act(acc, b1, smc, SAc, w, lane);
    // layer2: bufs 1,0
    zero_acc(acc);
    for (int c = 0; c < 2; c++) {
        CPA_W0(); __syncthreads();
        if (c < 1) cpaB(w2, 128, 64, sbB[0], tid);
        mma_chunk(aW + (uint32_t)(c * 64) * 2, sbB[(c + 1) & 1] + bo, acc, SAc * 2);
    }
    __syncthreads();
    cpaB(w3, 128, 0, sbB[1], tid);
    epi_act(acc, b2, smc, SAc, w, lane);
    // layer3: bufs 1,0
    zero_acc(acc);
    for (int c = 0; c < 2; c++) {
        CPA_W0(); __syncthreads();
        if (c < 1) cpaB(w3, 128, 64, sbB[0], tid);
        mma_chunk(aW + (uint32_t)(c * 64) * 2, sbB[(c + 1) & 1] + bo, acc, SAc * 2);
    }
    epi_ln(acc, b3, gam, bet, s_red, rowbase, nrows, out1h, resid, out2, w, lane);
}

// ---------------- EdgeBlock: [ea | xc[s] | xc[r]](384) -> 128 -> 128 -> LN ----------------
__global__ void __launch_bounds__(T, 3) k_edge(
    const __half* __restrict__ eah, const float* __restrict__ ea32,
    const __half* __restrict__ xch, const int* __restrict__ ei,
    const __half* __restrict__ w1, const __half* __restrict__ w2, const __half* __restrict__ w3,
    const float* __restrict__ b1, const float* __restrict__ b2, const float* __restrict__ b3,
    const float* __restrict__ gam, const float* __restrict__ bet,
    float* out2, int E)
{
    extern __shared__ char smc[];
    uint32_t sa = smem_u32(smc);
    uint32_t sbB[2] = { sa + E_B0, sa + E_B1 };
    float* s_red = (float*)(smc + E_RED);
    int tid = threadIdx.x, w = tid >> 5, lane = tid & 31;
    int rg = w & 1, cg = w >> 1;
    int rowbase = blockIdx.x * 64;
    int arow = (lane & 7) + ((lane >> 3) & 1) * 8;
    int acol = (lane >> 4) * 8;
    int b_r = (lane & 7) + (lane >> 4) * 8;
    int b_c = ((lane >> 3) & 1) * 8;
    uint32_t aW = sa + (uint32_t)((rg * 32 + arow) * SAe + acol) * 2;
    uint32_t bo = (uint32_t)((cg * 64 + b_r) * SB + b_c) * 2;
    float acc[2][8][4];

    // layer1: K=384, 6 chunks; A segs ping-pong: seg0(ea)->A0, seg1(xc[s])->A1, seg2(xc[r])->A0
    cpaH(eah, Hdim, 16, rowbase, E, sa, SAe, tid);
    cpaB(w1, 384, 0, sbB[0], tid);
    zero_acc(acc);
    for (int c = 0; c < 6; c++) {
        if (c == 1 || c == 3) { CPA_W1(); } else { CPA_W0(); }
        __syncthreads();
        if (c < 5) cpaB(w1, 384, (c + 1) * 64, sbB[(c + 1) & 1], tid);
        if (c == 0) cpaGh(xch, ei,     rowbase, sa + 128u * 2, SAe, tid);  // seg1 -> A cols 128-255
        if (c == 2) cpaGh(xch, ei + E, rowbase, sa, SAe, tid);             // seg2 -> A cols 0-127
        uint32_t aoff = (uint32_t)((((c >> 1) & 1) * 128) + (c & 1) * 64) * 2;
        mma_chunk(aW + aoff, sbB[c & 1] + bo, acc, SAe * 2);
    }
    __syncthreads();
    cpaB(w2, 128, 0, sbB[0], tid);
    epi_act(acc, b1, smc, SAe, w, lane);
    // layer2: bufs 0,1
    zero_acc(acc);
    for (int c = 0; c < 2; c++) {
        CPA_W0(); __syncthreads();
        if (c < 1) cpaB(w2, 128, 64, sbB[1], tid);
        mma_chunk(aW + (uint32_t)(c * 64) * 2, sbB[c & 1] + bo, acc, SAe * 2);
    }
    __syncthreads();
    cpaB(w3, 128, 0, sbB[0], tid);
    epi_act(acc, b2, smc, SAe, w, lane);
    // layer3: bufs 0,1
    zero_acc(acc);
    for (int c = 0; c < 2; c++) {
        CPA_W0(); __syncthreads();
        if (c < 1) cpaB(w3, 128, 64, sbB[1], tid);
        mma_chunk(aW + (uint32_t)(c * 64) * 2, sbB[c & 1] + bo, acc, SAe * 2);
    }
    epi_ln(acc, b3, gam, bet, s_red, rowbase, E, nullptr, ea32, out2, w, lane);
}

// ---------------- host ----------------
extern "C" void kernel_launch(void* const* d_in, const int* in_sizes, int n_in,
                              void* d_out, int out_size)
{
    const float* x     = (const float*)d_in[0];
    const float* ea    = (const float*)d_in[1];
    const float* cb_w1 = (const float*)d_in[2];
    const float* cb_b1 = (const float*)d_in[3];
    const float* cb_w2 = (const float*)d_in[4];
    const float* cb_b2 = (const float*)d_in[5];
    const float* cb_w3 = (const float*)d_in[6];
    const float* cb_b3 = (const float*)d_in[7];
    const float* cb_g  = (const float*)d_in[8];
    const float* cb_be = (const float*)d_in[9];
    const float* eb_w1 = (const float*)d_in[10];
    const float* eb_b1 = (const float*)d_in[11];
    const float* eb_w2 = (const float*)d_in[12];
    const float* eb_b2 = (const float*)d_in[13];
    const float* eb_w3 = (const float*)d_in[14];
    const float* eb_b3 = (const float*)d_in[15];
    const float* eb_g  = (const float*)d_in[16];
    const float* eb_be = (const float*)d_in[17];
    const int*   ei    = (const int*)d_in[18];

    int N = in_sizes[0] / Hdim;
    int E = in_sizes[1] / Hdim;
    float* out_x = (float*)d_out;
    float* out_e = out_x + (size_t)N * Hdim;

    __half *xh, *aggh, *xc1h, *xc2h, *eah, *wt;
    float* agg;
    cudaGetSymbolAddress((void**)&xh, g_xh);
    cudaGetSymbolAddress((void**)&aggh, g_aggh);
    cudaGetSymbolAddress((void**)&xc1h, g_xc1h);
    cudaGetSymbolAddress((void**)&xc2h, g_xc2h);
    cudaGetSymbolAddress((void**)&eah, g_eah);
    cudaGetSymbolAddress((void**)&wt, g_wt);
    cudaGetSymbolAddress((void**)&agg, g_agg);

    cudaFuncSetAttribute(k_cell, cudaFuncAttributeMaxDynamicSharedMemorySize, SMEM_CELL);
    cudaFuncSetAttribute(k_edge, cudaFuncAttributeMaxDynamicSharedMemorySize, SMEM_EDGE);

    const int OCB1 = 0, OCB2 = 24576, OCB3 = 40960, OEB1 = 57344, OEB2 = 106496, OEB3 = 122880;

    k_prep_all<<<(139264 + 255) / 256, 256>>>(cb_w1, cb_w2, cb_w3, eb_w1, eb_w2, eb_w3);
    k_zero<<<(N * HALF / 4 + 255) / 256, 256>>>(N * HALF / 4);
    k_cvt<<<(N * 32 + 255) / 256, 256>>>(x, xh, N * 32);
    k_scatter<<<(E * 32 + 255) / 256, 256>>>(ea, ei, E);
    k_cvt<<<(N * 16 + 255) / 256, 256>>>(agg, aggh, N * 16);

    int cgrid = (N + 63) / 64;
    int egrid = (E + 63) / 64;

    k_cell<<<cgrid, T, SMEM_CELL>>>(xh, aggh, wt + OCB1, wt + OCB2, wt + OCB3,
        cb_b1, cb_b2, cb_b3, cb_g, cb_be, xc1h, nullptr, nullptr, N);
    k_cell<<<cgrid, T, SMEM_CELL>>>(xc1h, aggh, wt + OCB1, wt + OCB2, wt + OCB3,
        cb_b1, cb_b2, cb_b3, cb_g, cb_be, xc2h, x, out_x, N);

    k_edge<<<egrid, T, SMEM_EDGE>>>(eah, ea, xc2h, ei, wt + OEB1, wt + OEB2, wt + OEB3,
        eb_b1, eb_b2, eb_b3, eb_g, eb_be, out_e, E);
}